// round 13
// baseline (speedup 1.0000x reference)
#include <cuda_runtime.h>
#include <cuda_fp16.h>
#include <math.h>
#include <stdint.h>

#define E_DIM 1024
#define S_LEN 2048

// ---------------- scratch (no allocation allowed) ----------------
__device__ __half g_xh [8388608],  g_xl [8388608];   // x split (fp16 hi/lo)
__device__ __half g_wi [3145728];                    // w_in  single fp16
__device__ __half g_wo [1048576];                    // w_out single fp16
__device__ __half g_qkh[25165824], g_qkl[25165824];  // rope'd qkv hi/lo
__device__ __half g_qh [8388608],  g_ql [8388608];   // q2 hi/lo (scaled 0.125)
__device__ __half g_kh [8388608];                    // k2 single
__device__ __half g_vh [8388608];                    // v2 single
__device__ __half g_cth[8388608],  g_ctl[8388608];   // ctx hi/lo

// ---------------- helpers ----------------
__device__ __forceinline__ uint32_t smem_u32(const void* p) {
    uint32_t a;
    asm("{ .reg .u64 t; cvta.to.shared.u64 t, %1; cvt.u32.u64 %0, t; }" : "=r"(a) : "l"(p));
    return a;
}
__device__ __forceinline__ void cp16(uint32_t s, const void* g) {
    asm volatile("cp.async.cg.shared.global [%0], [%1], 16;" :: "r"(s), "l"(g));
}
__device__ __forceinline__ void ldsm4(uint32_t* r, uint32_t a) {
    asm volatile("ldmatrix.sync.aligned.m8n8.x4.shared.b16 {%0,%1,%2,%3}, [%4];"
        : "=r"(r[0]), "=r"(r[1]), "=r"(r[2]), "=r"(r[3]) : "r"(a));
}
__device__ __forceinline__ void ldsm4t(uint32_t* r, uint32_t a) {
    asm volatile("ldmatrix.sync.aligned.m8n8.x4.trans.shared.b16 {%0,%1,%2,%3}, [%4];"
        : "=r"(r[0]), "=r"(r[1]), "=r"(r[2]), "=r"(r[3]) : "r"(a));
}
__device__ __forceinline__ void mma_f16(float* c, const uint32_t* a, const uint32_t* b) {
    asm volatile("mma.sync.aligned.m16n8k16.row.col.f32.f16.f16.f32 "
        "{%0,%1,%2,%3}, {%4,%5,%6,%7}, {%8,%9}, {%0,%1,%2,%3};"
        : "+f"(c[0]), "+f"(c[1]), "+f"(c[2]), "+f"(c[3])
        : "r"(a[0]), "r"(a[1]), "r"(a[2]), "r"(a[3]), "r"(b[0]), "r"(b[1]));
}
__device__ __forceinline__ uint32_t cvt2h(float x, float y) {
    __half2 h = __floats2half2_rn(x, y);
    return *(uint32_t*)&h;
}
__device__ __forceinline__ void split2h(float x, float y, uint32_t& hi, uint32_t& lo) {
    __half hx = __float2half_rn(x), hy = __float2half_rn(y);
    __half lx = __float2half_rn(x - __half2float(hx));
    __half ly = __float2half_rn(y - __half2float(hy));
    unsigned short a = *(unsigned short*)&hx, b = *(unsigned short*)&hy;
    unsigned short c = *(unsigned short*)&lx, d = *(unsigned short*)&ly;
    hi = (uint32_t)a | ((uint32_t)b << 16);
    lo = (uint32_t)c | ((uint32_t)d << 16);
}

// ---------------- fp32 -> fp16 hi+lo split / single convert ----------------
__global__ void split16_kernel(const float* __restrict__ src,
                               __half* __restrict__ hi, __half* __restrict__ lo, int n4)
{
    int q = blockIdx.x * 256 + threadIdx.x;
    if (q >= n4) return;
    int i = q << 2;
    float4 v = *(const float4*)(src + i);
    uint32_t h0, l0, h1, l1;
    split2h(v.x, v.y, h0, l0);
    split2h(v.z, v.w, h1, l1);
    *(uint32_t*)(hi + i)     = h0;  *(uint32_t*)(hi + i + 2) = h1;
    *(uint32_t*)(lo + i)     = l0;  *(uint32_t*)(lo + i + 2) = l1;
}
__global__ void cvt16_kernel(const float* __restrict__ src, __half* __restrict__ dst, int n4)
{
    int q = blockIdx.x * 256 + threadIdx.x;
    if (q >= n4) return;
    int i = q << 2;
    float4 v = *(const float4*)(src + i);
    *(uint32_t*)(dst + i)     = cvt2h(v.x, v.y);
    *(uint32_t*)(dst + i + 2) = cvt2h(v.z, v.w);
}

// ---------------- mma.sync fp16 2-pass GEMM: C = A @ B^T + bias ----------------
// A = Ah + Al (fp16 split), B single fp16. 128 thr, 4 warps @ 64x64, CTA 128x128.
// OM=0: fp32 out.  OM=2: RoPE + fp16 hi/lo out.  OM=3: merged q2/k2/v2 routed out.
#define OPB       8192
#define STGB      (3 * OPB)
#define GEMM_SMEM (3 * STGB)     // 73728

__device__ __forceinline__ void issue_stage(uint32_t sb, int stg, int k0,
    const __half* Ahb, const __half* Alb, const __half* Bb,
    int lda, int ldb, int tid)
{
    uint32_t s = sb + (uint32_t)stg * STGB;
    const int c = tid & 3;
    const int r0 = tid >> 2;               // 0..31
    const int kb8 = k0 + c * 8;
#pragma unroll
    for (int i = 0; i < 4; i++) {
        const int r = r0 + i * 32;
        const uint32_t so = (uint32_t)(r * 64 + ((c ^ ((r >> 1) & 3)) << 4));
        cp16(s +           so, Ahb + (size_t)r * lda + kb8);
        cp16(s + OPB +     so, Alb + (size_t)r * lda + kb8);
        cp16(s + 2 * OPB + so, Bb  + (size_t)r * ldb + kb8);
    }
    asm volatile("cp.async.commit_group;" ::: "memory");
}

template<int OM>
__global__ __launch_bounds__(128, 2)
void gemm_mma(const __half* __restrict__ Ah, const __half* __restrict__ Al, int lda,
              const __half* __restrict__ B, int ldb,
              const float* __restrict__ bias, float* __restrict__ C,
              __half* __restrict__ Ch, __half* __restrict__ Cl,
              float scale, int ldc, int K)
{
    extern __shared__ char smraw[];
    const uint32_t sb = smem_u32(smraw);
    const int tid = threadIdx.x;
    const int l = tid & 31, w = tid >> 5;
    const int wm = (w >> 1) * 64, wn = (w & 1) * 64;
    const int mb = blockIdx.y * 128, nb = blockIdx.x * 128;
    const int seg = (OM == 3) ? (blockIdx.x >> 3) : 0;
    const int aoff = (OM == 3) ? (seg << 10) : 0;

    const __half* Ahb = Ah + (size_t)mb * lda + aoff;
    const __half* Alb = Al + (size_t)mb * lda + aoff;
    const __half* Bb  = B  + (size_t)nb * ldb;

    const int rA = l & 15, kselA = l >> 4, swA = (rA >> 1) & 3;
    const uint32_t aRow = (uint32_t)((wm + rA) * 64);
    const uint32_t aK0 = (uint32_t)(((0 + kselA) ^ swA) << 4);
    const uint32_t aK1 = (uint32_t)(((2 + kselA) ^ swA) << 4);
    const int rB = (l & 7) + ((l >> 4) << 3), kselB = (l >> 3) & 1, swB = (rB >> 1) & 3;
    const uint32_t bRow = (uint32_t)((wn + rB) * 64);
    const uint32_t bK0 = (uint32_t)(((0 + kselB) ^ swB) << 4);
    const uint32_t bK1 = (uint32_t)(((2 + kselB) ^ swB) << 4);

    float acc[4][8][4];
#pragma unroll
    for (int mi = 0; mi < 4; mi++)
#pragma unroll
        for (int ni = 0; ni < 8; ni++)
#pragma unroll
            for (int i = 0; i < 4; i++) acc[mi][ni][i] = 0.0f;

    const int NKB = K >> 5;
    issue_stage(sb, 0, 0,  Ahb, Alb, Bb, lda, ldb, tid);
    issue_stage(sb, 1, 32, Ahb, Alb, Bb, lda, ldb, tid);

    for (int kb = 0; kb < NKB; kb++) {
        if (kb < NKB - 2) asm volatile("cp.async.wait_group 1;" ::: "memory");
        else              asm volatile("cp.async.wait_group 0;" ::: "memory");
        __syncthreads();
        if (kb + 2 < NKB)
            issue_stage(sb, (kb + 2) % 3, (kb + 2) * 32, Ahb, Alb, Bb, lda, ldb, tid);

        const uint32_t s = sb + (uint32_t)(kb % 3) * STGB;
#pragma unroll
        for (int kk = 0; kk < 2; kk++) {
            const uint32_t aK = kk ? aK1 : aK0;
            const uint32_t bK = kk ? bK1 : bK0;
            uint32_t ah[4][4], al4[4][4];
#pragma unroll
            for (int mi = 0; mi < 4; mi++) {
                ldsm4(ah[mi],  s +       aRow + mi * 1024 + aK);
                ldsm4(al4[mi], s + OPB + aRow + mi * 1024 + aK);
            }
#pragma unroll
            for (int g = 0; g < 4; g++) {
                uint32_t bh[4];
                ldsm4(bh, s + 2 * OPB + bRow + g * 1024 + bK);
#pragma unroll
                for (int mi = 0; mi < 4; mi++)
#pragma unroll
                    for (int nk = 0; nk < 2; nk++) {
                        float* c = acc[mi][g * 2 + nk];
                        mma_f16(c, ah[mi],  &bh[nk * 2]);
                        mma_f16(c, al4[mi], &bh[nk * 2]);
                    }
            }
        }
    }

    const int cr = l >> 2, cc2 = (l & 3) * 2;

    if (OM == 2) {
        // ---- fused RoPE + split epilogue (GEMM1) ----
        __syncthreads();
        float* sE = (float*)smraw;             // 128 x 132 fp32 staging (67.6KB <= 72KB)
#pragma unroll
        for (int ni = 0; ni < 8; ni++) {
            const int colg = nb + wn + ni * 8 + cc2;
            const float b0 = bias[colg], b1 = bias[colg + 1];
            const int colL = wn + ni * 8 + cc2;
#pragma unroll
            for (int mi = 0; mi < 4; mi++) {
                const int rowL = wm + mi * 16 + cr;
                sE[rowL * 132 + colL]           = acc[mi][ni][0] + b0;
                sE[rowL * 132 + colL + 1]       = acc[mi][ni][1] + b1;
                sE[(rowL + 8) * 132 + colL]     = acc[mi][ni][2] + b0;
                sE[(rowL + 8) * 132 + colL + 1] = acc[mi][ni][3] + b1;
            }
        }
        __syncthreads();
        const bool doRope = (blockIdx.x < 16);      // q,k tiles; v tiles pass through
        const int i0 = (tid & 15) << 1;
        const int hh = (tid >> 4) & 1;
        const int rb0 = tid >> 5;                   // 0..3
        const float invA = (float)exp2(-(double)i0 * 0.41524101186091903);
        const float invB = (float)exp2(-(double)(i0 + 1) * 0.41524101186091903);
        const int colL = hh * 64 + i0;
#pragma unroll 4
        for (int rr = 0; rr < 32; rr++) {
            const int row = rb0 + (rr << 2);
            float cA = 1.0f, sA = 0.0f, cB = 1.0f, sB = 0.0f;
            if (doRope) {
                const float sPos = (float)((mb + row) & (S_LEN - 1));
                sincosf(sPos * invA, &sA, &cA);
                sincosf(sPos * invB, &sB, &cB);
            }
            float2 x0 = *(float2*)&sE[row * 132 + colL];
            float2 x1 = *(float2*)&sE[row * 132 + colL + 32];
            float r00 = x0.x * cA - x1.x * sA, r01 = x0.y * cB - x1.y * sB;
            float r10 = x1.x * cA + x0.x * sA, r11 = x1.y * cB + x0.y * sB;
            uint32_t h0, l0, h1, l1;
            split2h(r00, r01, h0, l0);
            split2h(r10, r11, h1, l1);
            const size_t base = (size_t)(mb + row) * ldc + nb + colL;
            *(uint32_t*)(Ch + base)      = h0;
            *(uint32_t*)(Cl + base)      = l0;
            *(uint32_t*)(Ch + base + 32) = h1;
            *(uint32_t*)(Cl + base + 32) = l1;
        }
        return;
    }

    if (OM == 3) {
        // ---- merged q2/k2/v2 epilogue: seg0 -> qh/ql split, seg1 -> kh, seg2 -> vh ----
        const float sc = (seg == 0) ? 0.125f : 1.0f;
        const int nbo = nb - (seg << 10);
#pragma unroll
        for (int ni = 0; ni < 8; ni++) {
            const int colg = nb + wn + ni * 8 + cc2;
            const float b0 = bias[colg], b1 = bias[colg + 1];
            const int col = nbo + wn + ni * 8 + cc2;
#pragma unroll
            for (int mi = 0; mi < 4; mi++) {
                const int row = mb + wm + mi * 16 + cr;
                float v0 = (acc[mi][ni][0] + b0) * sc, v1 = (acc[mi][ni][1] + b1) * sc;
                float v2 = (acc[mi][ni][2] + b0) * sc, v3 = (acc[mi][ni][3] + b1) * sc;
                if (seg == 0) {
                    uint32_t h0, l0, h1, l1;
                    split2h(v0, v1, h0, l0);
                    split2h(v2, v3, h1, l1);
                    *(uint32_t*)(g_qh + (size_t)row * 1024 + col) = h0;
                    *(uint32_t*)(g_ql + (size_t)row * 1024 + col) = l0;
                    *(uint32_t*)(g_qh + (size_t)(row + 8) * 1024 + col) = h1;
                    *(uint32_t*)(g_ql + (size_t)(row + 8) * 1024 + col) = l1;
                } else {
                    __half* dst = (seg == 1) ? g_kh : g_vh;
                    *(uint32_t*)(dst + (size_t)row * 1024 + col) = cvt2h(v0, v1);
                    *(uint32_t*)(dst + (size_t)(row + 8) * 1024 + col) = cvt2h(v2, v3);
                }
            }
        }
        return;
    }

    // OM == 0: fp32 out
#pragma unroll
    for (int ni = 0; ni < 8; ni++) {
        const int col = nb + wn + ni * 8 + cc2;
        const float b0 = bias[col], b1 = bias[col + 1];
#pragma unroll
        for (int mi = 0; mi < 4; mi++) {
            const int row = mb + wm + mi * 16 + cr;
            *(float2*)(C + (size_t)row * ldc + col) =
                make_float2(acc[mi][ni][0] + b0, acc[mi][ni][1] + b1);
            *(float2*)(C + (size_t)(row + 8) * ldc + col) =
                make_float2(acc[mi][ni][2] + b0, acc[mi][ni][3] + b1);
        }
    }
}

// ---------------- Flash attention, fp16 2-pass (Q,P split; K,V single) ----------------
// 128 threads, 64 q-rows/CTA, 64 k-cols/iter, 2-stage KV pipeline.
// smem: Qh[8K] Ql[8K] mask[2K] | 2 stages x {K,V}[8K each] = 50KB -> 3 CTAs/SM (reg-limited)
#define ATT_QL   8192
#define ATT_MASK 16384
#define ATT_KV   18432
#define ATT_STG  16384
#define ATT_SMEM (ATT_KV + 2 * ATT_STG)   // 51200
#define NITER    32

__global__ __launch_bounds__(128, 2)
void attn_mma(const __half* __restrict__ qh, const __half* __restrict__ ql,
              const __half* __restrict__ kh, const __half* __restrict__ vh,
              const unsigned char* __restrict__ maskg,
              __half* __restrict__ Oh, __half* __restrict__ Ol)
{
    extern __shared__ char sm[];
    const uint32_t sb = smem_u32(sm);
    const int tid = threadIdx.x, l = tid & 31, w = tid >> 5;
    const int b = blockIdx.z, h = blockIdx.y, q0 = blockIdx.x << 6;
    const size_t rowbase = (size_t)b * S_LEN;
    const int h64 = h << 6;

    {
        const int tile = tid >> 6;
        const __half* src = tile ? ql : qh;
        const uint32_t dstb = sb + tile * ATT_QL;
        const int base = tid & 63;
#pragma unroll
        for (int i = 0; i < 8; i++) {
            int idx = base + i * 64; int r = idx >> 3, c = idx & 7;
            cp16(dstb + r * 128 + ((c ^ (r & 7)) << 4),
                 src + (rowbase + q0 + r) * 1024 + h64 + c * 8);
        }
        cp16(sb + ATT_MASK + tid * 16, maskg + (size_t)b * S_LEN + tid * 16);
    }
    const int kvt = tid >> 6;                      // 0 = K, 1 = V
    const __half* kvsrc = kvt ? vh : kh;
    const int kvb = tid & 63;
#define LOAD_KV(stg, kb) do {                                                     \
        uint32_t dstb = sb + ATT_KV + (stg) * ATT_STG + kvt * 8192;               \
        _Pragma("unroll")                                                         \
        for (int i = 0; i < 8; i++) {                                             \
            int idx = kvb + i * 64; int r = idx >> 3, c = idx & 7;                \
            cp16(dstb + r * 128 + ((c ^ (r & 7)) << 4),                           \
                 kvsrc + (rowbase + (kb) + r) * 1024 + h64 + c * 8);              \
        }                                                                         \
        asm volatile("cp.async.commit_group;" ::: "memory");                      \
    } while (0)

    LOAD_KV(0, 0);
    LOAD_KV(1, 64);

    asm volatile("cp.async.wait_group 1;" ::: "memory");
    __syncthreads();

    uint32_t qfh[4][4], qfl[4][4];
    {
        int row = (w << 4) + (l & 15);
#pragma unroll
        for (int j = 0; j < 4; j++) {
            uint32_t ch = (uint32_t)(((2 * j + (l >> 4)) ^ (row & 7)) << 4);
            ldsm4(qfh[j], sb +          row * 128 + ch);
            ldsm4(qfl[j], sb + ATT_QL + row * 128 + ch);
        }
    }

    float o[8][4];
#pragma unroll
    for (int di = 0; di < 8; di++)
#pragma unroll
        for (int i = 0; i < 4; i++) o[di][i] = 0.0f;
    float m0 = -1e30f, m1 = -1e30f, l0 = 0.0f, l1 = 0.0f;

    const unsigned char* Ms = (const unsigned char*)sm + ATT_MASK;

    for (int kt = 0; kt < NITER; kt++) {
        if (kt > 0) {
            if (kt < 30) asm volatile("cp.async.wait_group 1;" ::: "memory");
            else         asm volatile("cp.async.wait_group 0;" ::: "memory");
            __syncthreads();
        }
        const uint32_t stg = sb + ATT_KV + (uint32_t)(kt & 1) * ATT_STG;
        const int kb = kt << 6;

        // ---- S = Q K^T (2-pass: Qh, Ql vs single K) ----
        float S[8][4];
#pragma unroll
        for (int ni = 0; ni < 8; ni++)
#pragma unroll
            for (int i = 0; i < 4; i++) S[ni][i] = 0.0f;

#pragma unroll
        for (int j = 0; j < 4; j++) {
            uint32_t bh4[4][4];
#pragma unroll
            for (int ng = 0; ng < 4; ng++) {
                int row = (ng << 4) + (l & 7) + ((l >> 4) << 3);
                uint32_t ch = (uint32_t)(((2 * j + ((l >> 3) & 1)) ^ (row & 7)) << 4);
                ldsm4(bh4[ng], stg + row * 128 + ch);
            }
#pragma unroll
            for (int ni = 0; ni < 8; ni++) {
                uint32_t* bp = &bh4[ni >> 1][(ni & 1) * 2];
                mma_f16(S[ni], qfh[j], bp);
                mma_f16(S[ni], qfl[j], bp);
            }
        }

        // ---- mask + online softmax ----
        float tm0 = -1e30f, tm1 = -1e30f;
#pragma unroll
        for (int ni = 0; ni < 8; ni++) {
            uchar2 mm = *(const uchar2*)(Ms + kb + (ni << 3) + ((l & 3) << 1));
            if (mm.x) { S[ni][0] = -1e30f; S[ni][2] = -1e30f; }
            if (mm.y) { S[ni][1] = -1e30f; S[ni][3] = -1e30f; }
            tm0 = fmaxf(tm0, fmaxf(S[ni][0], S[ni][1]));
            tm1 = fmaxf(tm1, fmaxf(S[ni][2], S[ni][3]));
        }
        tm0 = fmaxf(tm0, __shfl_xor_sync(0xffffffffu, tm0, 1));
        tm0 = fmaxf(tm0, __shfl_xor_sync(0xffffffffu, tm0, 2));
        tm1 = fmaxf(tm1, __shfl_xor_sync(0xffffffffu, tm1, 1));
        tm1 = fmaxf(tm1, __shfl_xor_sync(0xffffffffu, tm1, 2));
        float mn0 = fmaxf(m0, tm0), mn1 = fmaxf(m1, tm1);
        float c0 = __expf(m0 - mn0), c1 = __expf(m1 - mn1);
        m0 = mn0; m1 = mn1;
        float rs0 = 0.0f, rs1 = 0.0f;
#pragma unroll
        for (int ni = 0; ni < 8; ni++) {
            S[ni][0] = __expf(S[ni][0] - mn0); rs0 += S[ni][0];
            S[ni][1] = __expf(S[ni][1] - mn0); rs0 += S[ni][1];
            S[ni][2] = __expf(S[ni][2] - mn1); rs1 += S[ni][2];
            S[ni][3] = __expf(S[ni][3] - mn1); rs1 += S[ni][3];
        }
        rs0 += __shfl_xor_sync(0xffffffffu, rs0, 1);
        rs0 += __shfl_xor_sync(0xffffffffu, rs0, 2);
        rs1 += __shfl_xor_sync(0xffffffffu, rs1, 1);
        rs1 += __shfl_xor_sync(0xffffffffu, rs1, 2);
        l0 = l0 * c0 + rs0; l1 = l1 * c1 + rs1;
#pragma unroll
        for (int di = 0; di < 8; di++) {
            o[di][0] *= c0; o[di][1] *= c0; o[di][2] *= c1; o[di][3] *= c1;
        }

        // ---- O += P V (2-pass: Ph, Pl vs single V) ----
#pragma unroll
        for (int js = 0; js < 4; js++) {
            uint32_t pha[4], pla[4];
            {
                const int t0 = 2 * js, t1 = t0 + 1;
                split2h(S[t0][0], S[t0][1], pha[0], pla[0]);
                split2h(S[t0][2], S[t0][3], pha[1], pla[1]);
                split2h(S[t1][0], S[t1][1], pha[2], pla[2]);
                split2h(S[t1][2], S[t1][3], pha[3], pla[3]);
            }
            uint32_t vh4[4][4];
#pragma unroll
            for (int dg = 0; dg < 4; dg++) {
                int row = (js << 4) + (l & 7) + (((l >> 3) & 1) << 3);
                uint32_t ch = (uint32_t)(((2 * dg + (l >> 4)) ^ (row & 7)) << 4);
                ldsm4t(vh4[dg], stg + 8192 + row * 128 + ch);
            }
#pragma unroll
            for (int di = 0; di < 8; di++) {
                uint32_t* vp = &vh4[di >> 1][(di & 1) * 2];
                mma_f16(o[di], pha, vp);
                mma_f16(o[di], pla, vp);
            }
        }

        __syncthreads();
        if (kt + 2 < NITER) LOAD_KV(kt & 1, (kt + 2) << 6);
    }

    const float inv0 = 1.0f / l0, inv1 = 1.0f / l1;
    const int r0 = q0 + (w << 4) + (l >> 2);
#pragma unroll
    for (int di = 0; di < 8; di++) {
        const int col = h64 + (di << 3) + ((l & 3) << 1);
        uint32_t h0, lo0, h1, lo1;
        split2h(o[di][0] * inv0, o[di][1] * inv0, h0, lo0);
        split2h(o[di][2] * inv1, o[di][3] * inv1, h1, lo1);
        *(uint32_t*)(Oh + (rowbase + r0) * 1024 + col) = h0;
        *(uint32_t*)(Ol + (rowbase + r0) * 1024 + col) = lo0;
        *(uint32_t*)(Oh + (rowbase + r0 + 8) * 1024 + col) = h1;
        *(uint32_t*)(Ol + (rowbase + r0 + 8) * 1024 + col) = lo1;
    }
}

// ---------------- launch ----------------
extern "C" void kernel_launch(void* const* d_in, const int* in_sizes, int n_in,
                              void* d_out, int out_size)
{
    const float* x     = (const float*)d_in[0];
    const float* w_in  = (const float*)d_in[1];
    const float* b_in  = (const float*)d_in[2];
    const float* w_out = (const float*)d_in[3];
    const float* b_out = (const float*)d_in[4];
    const unsigned char* mask = (const unsigned char*)d_in[5];
    float* out = (float*)d_out;

    __half *xh, *xl, *wi, *wo, *qkh, *qkl, *qh, *ql, *kh, *vh, *cth, *ctl;
    cudaGetSymbolAddress((void**)&xh,  g_xh);  cudaGetSymbolAddress((void**)&xl,  g_xl);
    cudaGetSymbolAddress((void**)&wi,  g_wi);  cudaGetSymbolAddress((void**)&wo,  g_wo);
    cudaGetSymbolAddress((void**)&qkh, g_qkh); cudaGetSymbolAddress((void**)&qkl, g_qkl);
    cudaGetSymbolAddress((void**)&qh,  g_qh);  cudaGetSymbolAddress((void**)&ql,  g_ql);
    cudaGetSymbolAddress((void**)&kh,  g_kh);  cudaGetSymbolAddress((void**)&vh,  g_vh);
    cudaGetSymbolAddress((void**)&cth, g_cth); cudaGetSymbolAddress((void**)&ctl, g_ctl);

    cudaFuncSetAttribute(gemm_mma<0>, cudaFuncAttributeMaxDynamicSharedMemorySize, GEMM_SMEM);
    cudaFuncSetAttribute(gemm_mma<2>, cudaFuncAttributeMaxDynamicSharedMemorySize, GEMM_SMEM);
    cudaFuncSetAttribute(gemm_mma<3>, cudaFuncAttributeMaxDynamicSharedMemorySize, GEMM_SMEM);
    cudaFuncSetAttribute(attn_mma,    cudaFuncAttributeMaxDynamicSharedMemorySize, ATT_SMEM);

    // input conversions
    split16_kernel<<<8192, 256>>>(x, xh, xl, 2097152);
    cvt16_kernel<<<3072, 256>>>(w_in,  wi, 786432);
    cvt16_kernel<<<1024, 256>>>(w_out, wo, 262144);

    // 1) qkv = x @ Win^T + b with fused RoPE + split -> qkh/qkl (fp16)
    gemm_mma<2><<<dim3(24, 64), 128, GEMM_SMEM>>>(xh, xl, 1024, wi, 1024,
                                                  b_in, nullptr, qkh, qkl, 1.0f, 3072, 1024);
    // 2) merged second projection -> qh/ql (split, x0.125), kh, vh (single)
    gemm_mma<3><<<dim3(24, 64), 128, GEMM_SMEM>>>(qkh, qkl, 3072, wi, 1024,
                                                  b_in, nullptr, nullptr, nullptr, 1.0f, 1024, 1024);
    // 3) attention -> ctx hi/lo (fp16)
    attn_mma<<<dim3(32, 16, 4), 128, ATT_SMEM>>>(qh, ql, kh, vh, mask, cth, ctl);
    // 4) out = ctx @ Wout^T + b (fp32 out)
    gemm_mma<0><<<dim3(8, 64), 128, GEMM_SMEM>>>(cth, ctl, 1024, wo, 1024,
                                                 b_out, out, nullptr, nullptr, 1.0f, 1024, 1024);
}

// round 14
// speedup vs baseline: 1.1092x; 1.1092x over previous
#include <cuda_runtime.h>
#include <cuda_bf16.h>
#include <math.h>
#include <stdint.h>

#define E_DIM 1024
#define S_LEN 2048

// ---------------- scratch (no allocation allowed) ----------------
__device__ __nv_bfloat16 g_xh [8388608],  g_xl [8388608];
__device__ __nv_bfloat16 g_wih[3145728],  g_wil[3145728];
__device__ __nv_bfloat16 g_woh[1048576],  g_wol[1048576];
__device__ __nv_bfloat16 g_qkh[25165824], g_qkl[25165824];  // rope'd qkv hi/lo
__device__ __nv_bfloat16 g_qh [8388608],  g_ql [8388608];   // q2 hi/lo (scaled 0.125)
__device__ __nv_bfloat16 g_kh [8388608],  g_kl [8388608];
__device__ __nv_bfloat16 g_vh [8388608],  g_vl [8388608];
__device__ __nv_bfloat16 g_cth[8388608],  g_ctl[8388608];   // ctx hi/lo

// ---------------- helpers ----------------
__device__ __forceinline__ uint32_t smem_u32(const void* p) {
    uint32_t a;
    asm("{ .reg .u64 t; cvta.to.shared.u64 t, %1; cvt.u32.u64 %0, t; }" : "=r"(a) : "l"(p));
    return a;
}
__device__ __forceinline__ void cp16(uint32_t s, const void* g) {
    asm volatile("cp.async.cg.shared.global [%0], [%1], 16;" :: "r"(s), "l"(g));
}
__device__ __forceinline__ void ldsm4(uint32_t* r, uint32_t a) {
    asm volatile("ldmatrix.sync.aligned.m8n8.x4.shared.b16 {%0,%1,%2,%3}, [%4];"
        : "=r"(r[0]), "=r"(r[1]), "=r"(r[2]), "=r"(r[3]) : "r"(a));
}
__device__ __forceinline__ void ldsm4t(uint32_t* r, uint32_t a) {
    asm volatile("ldmatrix.sync.aligned.m8n8.x4.trans.shared.b16 {%0,%1,%2,%3}, [%4];"
        : "=r"(r[0]), "=r"(r[1]), "=r"(r[2]), "=r"(r[3]) : "r"(a));
}
__device__ __forceinline__ void mma_bf16(float* c, const uint32_t* a, const uint32_t* b) {
    asm volatile("mma.sync.aligned.m16n8k16.row.col.f32.bf16.bf16.f32 "
        "{%0,%1,%2,%3}, {%4,%5,%6,%7}, {%8,%9}, {%0,%1,%2,%3};"
        : "+f"(c[0]), "+f"(c[1]), "+f"(c[2]), "+f"(c[3])
        : "r"(a[0]), "r"(a[1]), "r"(a[2]), "r"(a[3]), "r"(b[0]), "r"(b[1]));
}
__device__ __forceinline__ uint32_t pack2(__nv_bfloat16 a, __nv_bfloat16 b) {
    unsigned short ua = *(unsigned short*)&a, ub = *(unsigned short*)&b;
    return (uint32_t)ua | ((uint32_t)ub << 16);
}
__device__ __forceinline__ void split2(float x, float y, uint32_t& hi, uint32_t& lo) {
    __nv_bfloat16 hx = __float2bfloat16_rn(x);
    __nv_bfloat16 hy = __float2bfloat16_rn(y);
    __nv_bfloat16 lx = __float2bfloat16_rn(x - __bfloat162float(hx));
    __nv_bfloat16 ly = __float2bfloat16_rn(y - __bfloat162float(hy));
    hi = pack2(hx, hy); lo = pack2(lx, ly);
}

// ---------------- split fp32 -> bf16 hi + bf16 lo ----------------
__global__ void split_kernel(const float* __restrict__ src,
                             __nv_bfloat16* __restrict__ hi,
                             __nv_bfloat16* __restrict__ lo, int n4)
{
    int q = blockIdx.x * 256 + threadIdx.x;
    if (q >= n4) return;
    int i = q << 2;
    float4 v = *(const float4*)(src + i);
    uint32_t h0, l0, h1, l1;
    split2(v.x, v.y, h0, l0);
    split2(v.z, v.w, h1, l1);
    *(uint32_t*)(hi + i)     = h0;  *(uint32_t*)(hi + i + 2) = h1;
    *(uint32_t*)(lo + i)     = l0;  *(uint32_t*)(lo + i + 2) = l1;
}

// ---------------- mma.sync bf16x2 GEMM (R12 proven): C = A @ B^T + bias ----------------
// 128 threads, 4 warps @ 64x64, CTA 128x128, 3-stage pipeline.
// OM=0: fp32 out.  OM=2: RoPE + bf16 hi/lo out.  OM=3: merged q2/k2/v2 routed out.
#define OPB       8192
#define STGB      (4 * OPB)
#define GEMM_SMEM (3 * STGB)

__device__ __forceinline__ void issue_stage(uint32_t sb, int stg, int k0,
    const __nv_bfloat16* Ahb, const __nv_bfloat16* Alb,
    const __nv_bfloat16* Bhb, const __nv_bfloat16* Blb,
    int lda, int ldb, int tid)
{
    uint32_t s = sb + (uint32_t)stg * STGB;
    const int c = tid & 3;
    const int r0 = tid >> 2;               // 0..31
    const int kb8 = k0 + c * 8;
#pragma unroll
    for (int i = 0; i < 4; i++) {
        const int r = r0 + i * 32;
        const uint32_t so = (uint32_t)(r * 64 + ((c ^ ((r >> 1) & 3)) << 4));
        cp16(s +           so, Ahb + (size_t)r * lda + kb8);
        cp16(s + OPB +     so, Alb + (size_t)r * lda + kb8);
        cp16(s + 2 * OPB + so, Bhb + (size_t)r * ldb + kb8);
        cp16(s + 3 * OPB + so, Blb + (size_t)r * ldb + kb8);
    }
    asm volatile("cp.async.commit_group;" ::: "memory");
}

template<int OM>
__global__ __launch_bounds__(128, 2)
void gemm_mma(const __nv_bfloat16* __restrict__ Ah, const __nv_bfloat16* __restrict__ Al, int lda,
              const __nv_bfloat16* __restrict__ Bh, const __nv_bfloat16* __restrict__ Bl, int ldb,
              const float* __restrict__ bias, float* __restrict__ C,
              __nv_bfloat16* __restrict__ Ch, __nv_bfloat16* __restrict__ Cl,
              float scale, int ldc, int K)
{
    extern __shared__ char smraw[];
    const uint32_t sb = smem_u32(smraw);
    const int tid = threadIdx.x;
    const int l = tid & 31, w = tid >> 5;
    const int wm = (w >> 1) * 64, wn = (w & 1) * 64;
    const int mb = blockIdx.y * 128, nb = blockIdx.x * 128;
    const int seg = (OM == 3) ? (blockIdx.x >> 3) : 0;
    const int aoff = (OM == 3) ? (seg << 10) : 0;

    const __nv_bfloat16* Ahb = Ah + (size_t)mb * lda + aoff;
    const __nv_bfloat16* Alb = Al + (size_t)mb * lda + aoff;
    const __nv_bfloat16* Bhb = Bh + (size_t)nb * ldb;
    const __nv_bfloat16* Blb = Bl + (size_t)nb * ldb;

    const int rA = l & 15, kselA = l >> 4, swA = (rA >> 1) & 3;
    const uint32_t aRow = (uint32_t)((wm + rA) * 64);
    const uint32_t aK0 = (uint32_t)(((0 + kselA) ^ swA) << 4);
    const uint32_t aK1 = (uint32_t)(((2 + kselA) ^ swA) << 4);
    const int rB = (l & 7) + ((l >> 4) << 3), kselB = (l >> 3) & 1, swB = (rB >> 1) & 3;
    const uint32_t bRow = (uint32_t)((wn + rB) * 64);
    const uint32_t bK0 = (uint32_t)(((0 + kselB) ^ swB) << 4);
    const uint32_t bK1 = (uint32_t)(((2 + kselB) ^ swB) << 4);

    float acc[4][8][4];
#pragma unroll
    for (int mi = 0; mi < 4; mi++)
#pragma unroll
        for (int ni = 0; ni < 8; ni++)
#pragma unroll
            for (int i = 0; i < 4; i++) acc[mi][ni][i] = 0.0f;

    const int NKB = K >> 5;
    issue_stage(sb, 0, 0,  Ahb, Alb, Bhb, Blb, lda, ldb, tid);
    issue_stage(sb, 1, 32, Ahb, Alb, Bhb, Blb, lda, ldb, tid);

    for (int kb = 0; kb < NKB; kb++) {
        if (kb < NKB - 2) asm volatile("cp.async.wait_group 1;" ::: "memory");
        else              asm volatile("cp.async.wait_group 0;" ::: "memory");
        __syncthreads();
        if (kb + 2 < NKB)
            issue_stage(sb, (kb + 2) % 3, (kb + 2) * 32,
                        Ahb, Alb, Bhb, Blb, lda, ldb, tid);

        const uint32_t s = sb + (uint32_t)(kb % 3) * STGB;
#pragma unroll
        for (int kk = 0; kk < 2; kk++) {
            const uint32_t aK = kk ? aK1 : aK0;
            const uint32_t bK = kk ? bK1 : bK0;
            uint32_t ah[4][4], al4[4][4];
#pragma unroll
            for (int mi = 0; mi < 4; mi++) {
                ldsm4(ah[mi],  s +       aRow + mi * 1024 + aK);
                ldsm4(al4[mi], s + OPB + aRow + mi * 1024 + aK);
            }
#pragma unroll
            for (int g = 0; g < 4; g++) {
                uint32_t bh[4], bl[4];
                ldsm4(bh, s + 2 * OPB + bRow + g * 1024 + bK);
                ldsm4(bl, s + 3 * OPB + bRow + g * 1024 + bK);
#pragma unroll
                for (int mi = 0; mi < 4; mi++)
#pragma unroll
                    for (int nk = 0; nk < 2; nk++) {
                        float* c = acc[mi][g * 2 + nk];
                        mma_bf16(c, ah[mi],  &bh[nk * 2]);
                        mma_bf16(c, ah[mi],  &bl[nk * 2]);
                        mma_bf16(c, al4[mi], &bh[nk * 2]);
                    }
            }
        }
    }

    const int cr = l >> 2, cc2 = (l & 3) * 2;

    if (OM == 2) {
        // ---- fused RoPE + split epilogue (GEMM1) ----
        __syncthreads();
        float* sE = (float*)smraw;             // 128 x 132 fp32 staging
#pragma unroll
        for (int ni = 0; ni < 8; ni++) {
            const int colg = nb + wn + ni * 8 + cc2;
            const float b0 = bias[colg], b1 = bias[colg + 1];
            const int colL = wn + ni * 8 + cc2;
#pragma unroll
            for (int mi = 0; mi < 4; mi++) {
                const int rowL = wm + mi * 16 + cr;
                sE[rowL * 132 + colL]           = acc[mi][ni][0] + b0;
                sE[rowL * 132 + colL + 1]       = acc[mi][ni][1] + b1;
                sE[(rowL + 8) * 132 + colL]     = acc[mi][ni][2] + b0;
                sE[(rowL + 8) * 132 + colL + 1] = acc[mi][ni][3] + b1;
            }
        }
        __syncthreads();
        const bool doRope = (blockIdx.x < 16);      // q,k tiles; v tiles pass through
        const int i0 = (tid & 15) << 1;
        const int hh = (tid >> 4) & 1;
        const int rb0 = tid >> 5;                   // 0..3
        const float invA = (float)exp2(-(double)i0 * 0.41524101186091903);
        const float invB = (float)exp2(-(double)(i0 + 1) * 0.41524101186091903);
        const int colL = hh * 64 + i0;
#pragma unroll 4
        for (int rr = 0; rr < 32; rr++) {
            const int row = rb0 + (rr << 2);
            float cA = 1.0f, sA = 0.0f, cB = 1.0f, sB = 0.0f;
            if (doRope) {
                const float sPos = (float)((mb + row) & (S_LEN - 1));
                sincosf(sPos * invA, &sA, &cA);
                sincosf(sPos * invB, &sB, &cB);
            }
            float2 x0 = *(float2*)&sE[row * 132 + colL];
            float2 x1 = *(float2*)&sE[row * 132 + colL + 32];
            float r00 = x0.x * cA - x1.x * sA, r01 = x0.y * cB - x1.y * sB;
            float r10 = x1.x * cA + x0.x * sA, r11 = x1.y * cB + x0.y * sB;
            uint32_t h0, l0, h1, l1;
            split2(r00, r01, h0, l0);
            split2(r10, r11, h1, l1);
            const size_t base = (size_t)(mb + row) * ldc + nb + colL;
            *(uint32_t*)(Ch + base)      = h0;
            *(uint32_t*)(Cl + base)      = l0;
            *(uint32_t*)(Ch + base + 32) = h1;
            *(uint32_t*)(Cl + base + 32) = l1;
        }
        return;
    }

    if (OM == 3) {
        // ---- merged q2/k2/v2 epilogue: route by segment ----
        __nv_bfloat16* Coh = (seg == 0) ? g_qh : (seg == 1) ? g_kh : g_vh;
        __nv_bfloat16* Col = (seg == 0) ? g_ql : (seg == 1) ? g_kl : g_vl;
        const float sc = (seg == 0) ? 0.125f : 1.0f;
        const int nbo = nb - (seg << 10);
#pragma unroll
        for (int ni = 0; ni < 8; ni++) {
            const int colg = nb + wn + ni * 8 + cc2;
            const float b0 = bias[colg], b1 = bias[colg + 1];
            const int col = nbo + wn + ni * 8 + cc2;
#pragma unroll
            for (int mi = 0; mi < 4; mi++) {
                const int row = mb + wm + mi * 16 + cr;
                float v0 = (acc[mi][ni][0] + b0) * sc, v1 = (acc[mi][ni][1] + b1) * sc;
                float v2 = (acc[mi][ni][2] + b0) * sc, v3 = (acc[mi][ni][3] + b1) * sc;
                uint32_t h0, l0, h1, l1;
                split2(v0, v1, h0, l0);
                split2(v2, v3, h1, l1);
                *(uint32_t*)(Coh + (size_t)row * 1024 + col) = h0;
                *(uint32_t*)(Col + (size_t)row * 1024 + col) = l0;
                *(uint32_t*)(Coh + (size_t)(row + 8) * 1024 + col) = h1;
                *(uint32_t*)(Col + (size_t)(row + 8) * 1024 + col) = l1;
            }
        }
        return;
    }

    // OM == 0: fp32 out
#pragma unroll
    for (int ni = 0; ni < 8; ni++) {
        const int col = nb + wn + ni * 8 + cc2;
        const float b0 = bias[col], b1 = bias[col + 1];
#pragma unroll
        for (int mi = 0; mi < 4; mi++) {
            const int row = mb + wm + mi * 16 + cr;
            *(float2*)(C + (size_t)row * ldc + col) =
                make_float2(acc[mi][ni][0] + b0, acc[mi][ni][1] + b1);
            *(float2*)(C + (size_t)(row + 8) * ldc + col) =
                make_float2(acc[mi][ni][2] + b0, acc[mi][ni][3] + b1);
        }
    }
}

// ---------------- Flash attention, bf16 3-pass, smem-overlapped Q -> 3 CTAs/SM ----------
// 128 threads, 64 q-rows/CTA, 64 k-cols/iter, 2-stage KV pipeline.
// smem layout: mask[0..2K) | stages at [2K..66K) (2 x 32K {Kh,Kl,Vh,Vl}).
// Q hi/lo (16K) is staged INSIDE stage-0 area during the prologue, read into
// registers, then overwritten by KV — total 66K -> 3 CTAs/SM.
#define ATT_MASK 0
#define ATT_KV   2048
#define ATT_STG  32768
#define ATT_SMEM (2048 + 2 * ATT_STG)   // 67584
#define NITER    32

__global__ __launch_bounds__(128, 3)
void attn_mma(const __nv_bfloat16* __restrict__ qh, const __nv_bfloat16* __restrict__ ql,
              const __nv_bfloat16* __restrict__ kh, const __nv_bfloat16* __restrict__ kl,
              const __nv_bfloat16* __restrict__ vh, const __nv_bfloat16* __restrict__ vl,
              const unsigned char* __restrict__ maskg,
              __nv_bfloat16* __restrict__ Oh, __nv_bfloat16* __restrict__ Ol)
{
    extern __shared__ char sm[];
    const uint32_t sb = smem_u32(sm);
    const int tid = threadIdx.x, l = tid & 31, w = tid >> 5;
    const int b = blockIdx.z, h = blockIdx.y, q0 = blockIdx.x << 6;
    const size_t rowbase = (size_t)b * S_LEN;
    const int h64 = h << 6;

    // ---- prologue phase 1: Q hi/lo (into stage-0 area) + mask ----
    {
        const int tile = tid >> 6;                  // 0: hi, 1: lo
        const __nv_bfloat16* src = tile ? ql : qh;
        const uint32_t dstb = sb + ATT_KV + tile * 8192;
        const int base = tid & 63;
#pragma unroll
        for (int i = 0; i < 8; i++) {
            int idx = base + i * 64; int r = idx >> 3, c = idx & 7;
            cp16(dstb + r * 128 + ((c ^ (r & 7)) << 4),
                 src + (rowbase + q0 + r) * 1024 + h64 + c * 8);
        }
        cp16(sb + ATT_MASK + tid * 16, maskg + (size_t)b * S_LEN + tid * 16);
        asm volatile("cp.async.commit_group;" ::: "memory");
    }
    asm volatile("cp.async.wait_group 0;" ::: "memory");
    __syncthreads();

    // ---- Q fragments (persistent), then release the smem for KV ----
    uint32_t qfh[4][4], qfl[4][4];
    {
        int row = (w << 4) + (l & 15);
#pragma unroll
        for (int j = 0; j < 4; j++) {
            uint32_t ch = (uint32_t)(((2 * j + (l >> 4)) ^ (row & 7)) << 4);
            ldsm4(qfh[j], sb + ATT_KV +        row * 128 + ch);
            ldsm4(qfl[j], sb + ATT_KV + 8192 + row * 128 + ch);
        }
    }
    __syncthreads();   // all warps done reading Q smem

    // ---- prologue phase 2: KV stages 0 and 1 (overwrites Q area) ----
    const int kvtile = tid >> 5;
    const __nv_bfloat16* kvsrc = (kvtile == 0) ? kh : (kvtile == 1) ? kl : (kvtile == 2) ? vh : vl;
    const int kvbase = tid & 31;
#define LOAD_KV(stg, kb) do {                                                     \
        uint32_t dstb = sb + ATT_KV + (stg) * ATT_STG + kvtile * 8192;            \
        _Pragma("unroll")                                                         \
        for (int i = 0; i < 16; i++) {                                            \
            int idx = kvbase + i * 32; int r = idx >> 3, c = idx & 7;             \
            cp16(dstb + r * 128 + ((c ^ (r & 7)) << 4),                           \
                 kvsrc + (rowbase + (kb) + r) * 1024 + h64 + c * 8);              \
        }                                                                         \
        asm volatile("cp.async.commit_group;" ::: "memory");                      \
    } while (0)

    LOAD_KV(0, 0);
    LOAD_KV(1, 64);

    float o[8][4];
#pragma unroll
    for (int di = 0; di < 8; di++)
#pragma unroll
        for (int i = 0; i < 4; i++) o[di][i] = 0.0f;
    float m0 = -1e30f, m1 = -1e30f, l0 = 0.0f, l1 = 0.0f;

    const unsigned char* Ms = (const unsigned char*)sm + ATT_MASK;

    for (int kt = 0; kt < NITER; kt++) {
        if (kt < NITER - 2) asm volatile("cp.async.wait_group 1;" ::: "memory");
        else                asm volatile("cp.async.wait_group 0;" ::: "memory");
        __syncthreads();
        const uint32_t stg = sb + ATT_KV + (uint32_t)(kt & 1) * ATT_STG;
        const int kb = kt << 6;

        // ---- S = Q K^T (3-pass split) ----
        float S[8][4];
#pragma unroll
        for (int ni = 0; ni < 8; ni++)
#pragma unroll
            for (int i = 0; i < 4; i++) S[ni][i] = 0.0f;

#pragma unroll
        for (int j = 0; j < 4; j++) {
            uint32_t bh4[4][4], bl4[4][4];
#pragma unroll
            for (int ng = 0; ng < 4; ng++) {
                int row = (ng << 4) + (l & 7) + ((l >> 4) << 3);
                uint32_t ch = (uint32_t)(((2 * j + ((l >> 3) & 1)) ^ (row & 7)) << 4);
                ldsm4(bh4[ng], stg +        row * 128 + ch);
                ldsm4(bl4[ng], stg + 8192 + row * 128 + ch);
            }
#pragma unroll
            for (int ni = 0; ni < 8; ni++) {
                uint32_t* bp = &bh4[ni >> 1][(ni & 1) * 2];
                uint32_t* lp = &bl4[ni >> 1][(ni & 1) * 2];
                mma_bf16(S[ni], qfh[j], bp);
                mma_bf16(S[ni], qfh[j], lp);
                mma_bf16(S[ni], qfl[j], bp);
            }
        }

        // ---- mask + online softmax ----
        float tm0 = -1e30f, tm1 = -1e30f;
#pragma unroll
        for (int ni = 0; ni < 8; ni++) {
            uchar2 mm = *(const uchar2*)(Ms + kb + (ni << 3) + ((l & 3) << 1));
            if (mm.x) { S[ni][0] = -1e30f; S[ni][2] = -1e30f; }
            if (mm.y) { S[ni][1] = -1e30f; S[ni][3] = -1e30f; }
            tm0 = fmaxf(tm0, fmaxf(S[ni][0], S[ni][1]));
            tm1 = fmaxf(tm1, fmaxf(S[ni][2], S[ni][3]));
        }
        tm0 = fmaxf(tm0, __shfl_xor_sync(0xffffffffu, tm0, 1));
        tm0 = fmaxf(tm0, __shfl_xor_sync(0xffffffffu, tm0, 2));
        tm1 = fmaxf(tm1, __shfl_xor_sync(0xffffffffu, tm1, 1));
        tm1 = fmaxf(tm1, __shfl_xor_sync(0xffffffffu, tm1, 2));
        float mn0 = fmaxf(m0, tm0), mn1 = fmaxf(m1, tm1);
        float c0 = __expf(m0 - mn0), c1 = __expf(m1 - mn1);
        m0 = mn0; m1 = mn1;
        float rs0 = 0.0f, rs1 = 0.0f;
#pragma unroll
        for (int ni = 0; ni < 8; ni++) {
            S[ni][0] = __expf(S[ni][0] - mn0); rs0 += S[ni][0];
            S[ni][1] = __expf(S[ni][1] - mn0); rs0 += S[ni][1];
            S[ni][2] = __expf(S[ni][2] - mn1); rs1 += S[ni][2];
            S[ni][3] = __expf(S[ni][3] - mn1); rs1 += S[ni][3];
        }
        rs0 += __shfl_xor_sync(0xffffffffu, rs0, 1);
        rs0 += __shfl_xor_sync(0xffffffffu, rs0, 2);
        rs1 += __shfl_xor_sync(0xffffffffu, rs1, 1);
        rs1 += __shfl_xor_sync(0xffffffffu, rs1, 2);
        l0 = l0 * c0 + rs0; l1 = l1 * c1 + rs1;
#pragma unroll
        for (int di = 0; di < 8; di++) {
            o[di][0] *= c0; o[di][1] *= c0; o[di][2] *= c1; o[di][3] *= c1;
        }

        // ---- O += P V (3-pass split; P in registers) ----
#pragma unroll
        for (int js = 0; js < 4; js++) {
            uint32_t pha[4], pla[4];
            {
                const int t0 = 2 * js, t1 = t0 + 1;
                split2(S[t0][0], S[t0][1], pha[0], pla[0]);
                split2(S[t0][2], S[t0][3], pha[1], pla[1]);
                split2(S[t1][0], S[t1][1], pha[2], pla[2]);
                split2(S[t1][2], S[t1][3], pha[3], pla[3]);
            }
            uint32_t vh4[4][4], vl4[4][4];
#pragma unroll
            for (int dg = 0; dg < 4; dg++) {
                int row = (js << 4) + (l & 7) + (((l >> 3) & 1) << 3);
                uint32_t ch = (uint32_t)(((2 * dg + (l >> 4)) ^ (row & 7)) << 4);
                ldsm4t(vh4[dg], stg + 16384 + row * 128 + ch);
                ldsm4t(vl4[dg], stg + 24576 + row * 128 + ch);
            }
#pragma unroll
            for (int di = 0; di < 8; di++) {
                uint32_t* vp = &vh4[di >> 1][(di & 1) * 2];
                uint32_t* lp = &vl4[di >> 1][(di & 1) * 2];
                mma_bf16(o[di], pha, vp);
                mma_bf16(o[di], pha, lp);
                mma_bf16(o[di], pla, vp);
            }
        }

        __syncthreads();
        if (kt + 2 < NITER) LOAD_KV(kt & 1, (kt + 2) << 6);
    }

    // ---- epilogue: normalize, split, store ----
    const float inv0 = 1.0f / l0, inv1 = 1.0f / l1;
    const int r0 = q0 + (w << 4) + (l >> 2);
#pragma unroll
    for (int di = 0; di < 8; di++) {
        const int col = h64 + (di << 3) + ((l & 3) << 1);
        uint32_t h0, lo0, h1, lo1;
        split2(o[di][0] * inv0, o[di][1] * inv0, h0, lo0);
        split2(o[di][2] * inv1, o[di][3] * inv1, h1, lo1);
        *(uint32_t*)(Oh + (rowbase + r0) * 1024 + col) = h0;
        *(uint32_t*)(Ol + (rowbase + r0) * 1024 + col) = lo0;
        *(uint32_t*)(Oh + (rowbase + r0 + 8) * 1024 + col) = h1;
        *(uint32_t*)(Ol + (rowbase + r0 + 8) * 1024 + col) = lo1;
    }
}

// ---------------- launch ----------------
extern "C" void kernel_launch(void* const* d_in, const int* in_sizes, int n_in,
                              void* d_out, int out_size)
{
    const float* x     = (const float*)d_in[0];
    const float* w_in  = (const float*)d_in[1];
    const float* b_in  = (const float*)d_in[2];
    const float* w_out = (const float*)d_in[3];
    const float* b_out = (const float*)d_in[4];
    const unsigned char* mask = (const unsigned char*)d_in[5];
    float* out = (float*)d_out;

    __nv_bfloat16 *xh, *xl, *wih, *wil, *woh, *wol, *qkh, *qkl;
    __nv_bfloat16 *qh, *ql, *kh, *kl, *vh, *vl, *cth, *ctl;
    cudaGetSymbolAddress((void**)&xh,  g_xh);  cudaGetSymbolAddress((void**)&xl,  g_xl);
    cudaGetSymbolAddress((void**)&wih, g_wih); cudaGetSymbolAddress((void**)&wil, g_wil);
    cudaGetSymbolAddress((void**)&woh, g_woh); cudaGetSymbolAddress((void**)&wol, g_wol);
    cudaGetSymbolAddress((void**)&qkh, g_qkh); cudaGetSymbolAddress((void**)&qkl, g_qkl);
    cudaGetSymbolAddress((void**)&qh,  g_qh);  cudaGetSymbolAddress((void**)&ql,  g_ql);
    cudaGetSymbolAddress((void**)&kh,  g_kh);  cudaGetSymbolAddress((void**)&kl,  g_kl);
    cudaGetSymbolAddress((void**)&vh,  g_vh);  cudaGetSymbolAddress((void**)&vl,  g_vl);
    cudaGetSymbolAddress((void**)&cth, g_cth); cudaGetSymbolAddress((void**)&ctl, g_ctl);

    cudaFuncSetAttribute(gemm_mma<0>, cudaFuncAttributeMaxDynamicSharedMemorySize, GEMM_SMEM);
    cudaFuncSetAttribute(gemm_mma<2>, cudaFuncAttributeMaxDynamicSharedMemorySize, GEMM_SMEM);
    cudaFuncSetAttribute(gemm_mma<3>, cudaFuncAttributeMaxDynamicSharedMemorySize, GEMM_SMEM);
    cudaFuncSetAttribute(attn_mma,    cudaFuncAttributeMaxDynamicSharedMemorySize, ATT_SMEM);

    // split inputs
    split_kernel<<<8192, 256>>>(x,     xh,  xl,  2097152);
    split_kernel<<<3072, 256>>>(w_in,  wih, wil, 786432);
    split_kernel<<<1024, 256>>>(w_out, woh, wol, 262144);

    // 1) qkv = x @ Win^T + b with fused RoPE + split -> qkh/qkl (8192 x 3072 bf16)
    gemm_mma<2><<<dim3(24, 64), 128, GEMM_SMEM>>>(xh, xl, 1024, wih, wil, 1024,
                                                  b_in, nullptr, qkh, qkl, 1.0f, 3072, 1024);
    // 2) merged second projection: one launch, outputs routed to qh/ql, kh/kl, vh/vl
    gemm_mma<3><<<dim3(24, 64), 128, GEMM_SMEM>>>(qkh, qkl, 3072, wih, wil, 1024,
                                                  b_in, nullptr, nullptr, nullptr, 1.0f, 1024, 1024);
    // 3) attention (3 CTAs/SM) -> ctx hi/lo
    attn_mma<<<dim3(32, 16, 4), 128, ATT_SMEM>>>(qh, ql, kh, kl, vh, vl, mask, cth, ctl);
    // 4) out = ctx @ Wout^T + b (fp32 out)
    gemm_mma<0><<<dim3(8, 64), 128, GEMM_SMEM>>>(cth, ctl, 1024, woh, wol, 1024,
                                                 b_out, out, nullptr, nullptr, 1.0f, 1024, 1024);
}

// round 15
// speedup vs baseline: 1.1933x; 1.0757x over previous
#include <cuda_runtime.h>
#include <cuda_bf16.h>
#include <math.h>
#include <stdint.h>

#define E_DIM 1024
#define S_LEN 2048

// ---------------- scratch (no allocation allowed) ----------------
__device__ __nv_bfloat16 g_xh [8388608],  g_xl [8388608];
__device__ __nv_bfloat16 g_wih[3145728],  g_wil[3145728];
__device__ __nv_bfloat16 g_woh[1048576],  g_wol[1048576];
__device__ __nv_bfloat16 g_qkh[25165824], g_qkl[25165824];  // rope'd q,k hi/lo (8192x2048)
__device__ __nv_bfloat16 g_qh [8388608],  g_ql [8388608];   // q2 hi/lo (scaled 0.125)
__device__ __nv_bfloat16 g_kh [8388608],  g_kl [8388608];
__device__ __nv_bfloat16 g_vh [8388608],  g_vl [8388608];
__device__ __nv_bfloat16 g_cth[8388608],  g_ctl[8388608];   // ctx hi/lo
__device__ __nv_bfloat16 g_wvth[1048576], g_wvtl[1048576];  // Wv^T hi/lo
__device__ __nv_bfloat16 g_wvvh[1048576], g_wvvl[1048576];  // Wvv = Wv@Wv hi/lo
__device__ float g_bvv[1024];                               // Wv@bv + bv
__device__ float g_zb [1024];                               // zeros (never written)

// ---------------- helpers ----------------
__device__ __forceinline__ uint32_t smem_u32(const void* p) {
    uint32_t a;
    asm("{ .reg .u64 t; cvta.to.shared.u64 t, %1; cvt.u32.u64 %0, t; }" : "=r"(a) : "l"(p));
    return a;
}
__device__ __forceinline__ void cp16(uint32_t s, const void* g) {
    asm volatile("cp.async.cg.shared.global [%0], [%1], 16;" :: "r"(s), "l"(g));
}
__device__ __forceinline__ void ldsm4(uint32_t* r, uint32_t a) {
    asm volatile("ldmatrix.sync.aligned.m8n8.x4.shared.b16 {%0,%1,%2,%3}, [%4];"
        : "=r"(r[0]), "=r"(r[1]), "=r"(r[2]), "=r"(r[3]) : "r"(a));
}
__device__ __forceinline__ void ldsm4t(uint32_t* r, uint32_t a) {
    asm volatile("ldmatrix.sync.aligned.m8n8.x4.trans.shared.b16 {%0,%1,%2,%3}, [%4];"
        : "=r"(r[0]), "=r"(r[1]), "=r"(r[2]), "=r"(r[3]) : "r"(a));
}
__device__ __forceinline__ void mma_bf16(float* c, const uint32_t* a, const uint32_t* b) {
    asm volatile("mma.sync.aligned.m16n8k16.row.col.f32.bf16.bf16.f32 "
        "{%0,%1,%2,%3}, {%4,%5,%6,%7}, {%8,%9}, {%0,%1,%2,%3};"
        : "+f"(c[0]), "+f"(c[1]), "+f"(c[2]), "+f"(c[3])
        : "r"(a[0]), "r"(a[1]), "r"(a[2]), "r"(a[3]), "r"(b[0]), "r"(b[1]));
}
__device__ __forceinline__ uint32_t pack2(__nv_bfloat16 a, __nv_bfloat16 b) {
    unsigned short ua = *(unsigned short*)&a, ub = *(unsigned short*)&b;
    return (uint32_t)ua | ((uint32_t)ub << 16);
}
__device__ __forceinline__ void split2(float x, float y, uint32_t& hi, uint32_t& lo) {
    __nv_bfloat16 hx = __float2bfloat16_rn(x);
    __nv_bfloat16 hy = __float2bfloat16_rn(y);
    __nv_bfloat16 lx = __float2bfloat16_rn(x - __bfloat162float(hx));
    __nv_bfloat16 ly = __float2bfloat16_rn(y - __bfloat162float(hy));
    hi = pack2(hx, hy); lo = pack2(lx, ly);
}

// ---------------- split fp32 -> bf16 hi + bf16 lo ----------------
__global__ void split_kernel(const float* __restrict__ src,
                             __nv_bfloat16* __restrict__ hi,
                             __nv_bfloat16* __restrict__ lo, int n4)
{
    int q = blockIdx.x * 256 + threadIdx.x;
    if (q >= n4) return;
    int i = q << 2;
    float4 v = *(const float4*)(src + i);
    uint32_t h0, l0, h1, l1;
    split2(v.x, v.y, h0, l0);
    split2(v.z, v.w, h1, l1);
    *(uint32_t*)(hi + i)     = h0;  *(uint32_t*)(hi + i + 2) = h1;
    *(uint32_t*)(lo + i)     = l0;  *(uint32_t*)(lo + i + 2) = l1;
}

// ---------------- transpose + split: dst[n][k] = src[k][n] (1024x1024 fp32) ----------------
__global__ void transpose_split_kernel(const float* __restrict__ src,
                                       __nv_bfloat16* __restrict__ th,
                                       __nv_bfloat16* __restrict__ tl)
{
    __shared__ float t[32][33];
    const int bx = blockIdx.x << 5, by = blockIdx.y << 5;
    const int x = threadIdx.x;
#pragma unroll
    for (int j = threadIdx.y; j < 32; j += 8)
        t[j][x] = src[(size_t)(by + j) * 1024 + bx + x];
    __syncthreads();
#pragma unroll
    for (int j = threadIdx.y; j < 32; j += 8) {
        float v = t[x][j];
        __nv_bfloat16 h = __float2bfloat16_rn(v);
        __nv_bfloat16 l = __float2bfloat16_rn(v - __bfloat162float(h));
        const size_t o = (size_t)(bx + j) * 1024 + by + x;
        th[o] = h; tl[o] = l;
    }
}

// ---------------- bvv[i] = bv[i] + sum_k Wv[i][k]*bv[k] ----------------
__global__ void bvv_kernel(const float* __restrict__ Wv, const float* __restrict__ bv,
                           float* __restrict__ bvv)
{
    __shared__ float red[8];
    const int row = blockIdx.x;
    float s = 0.0f;
    for (int k = threadIdx.x; k < 1024; k += 256)
        s += Wv[(size_t)row * 1024 + k] * bv[k];
#pragma unroll
    for (int off = 16; off; off >>= 1) s += __shfl_xor_sync(0xffffffffu, s, off);
    if ((threadIdx.x & 31) == 0) red[threadIdx.x >> 5] = s;
    __syncthreads();
    if (threadIdx.x == 0) {
        float t = 0.0f;
#pragma unroll
        for (int i = 0; i < 8; i++) t += red[i];
        bvv[row] = t + bv[row];
    }
}

// ---------------- mma.sync bf16x2 GEMM (R12 proven): C = A @ B^T + bias ----------------
// 128 threads, 4 warps @ 64x64, CTA 128x128, 3-stage pipeline.
// OM=0: fp32 out.  OM=1: bf16 hi/lo out to Ch/Cl (scale after bias).
// OM=2: RoPE + bf16 hi/lo out.  OM=3: q/k routed out (seg = blockIdx.x>>3 in {0,1}).
#define OPB       8192
#define STGB      (4 * OPB)
#define GEMM_SMEM (3 * STGB)

__device__ __forceinline__ void issue_stage(uint32_t sb, int stg, int k0,
    const __nv_bfloat16* Ahb, const __nv_bfloat16* Alb,
    const __nv_bfloat16* Bhb, const __nv_bfloat16* Blb,
    int lda, int ldb, int tid)
{
    uint32_t s = sb + (uint32_t)stg * STGB;
    const int c = tid & 3;
    const int r0 = tid >> 2;               // 0..31
    const int kb8 = k0 + c * 8;
#pragma unroll
    for (int i = 0; i < 4; i++) {
        const int r = r0 + i * 32;
        const uint32_t so = (uint32_t)(r * 64 + ((c ^ ((r >> 1) & 3)) << 4));
        cp16(s +           so, Ahb + (size_t)r * lda + kb8);
        cp16(s + OPB +     so, Alb + (size_t)r * lda + kb8);
        cp16(s + 2 * OPB + so, Bhb + (size_t)r * ldb + kb8);
        cp16(s + 3 * OPB + so, Blb + (size_t)r * ldb + kb8);
    }
    asm volatile("cp.async.commit_group;" ::: "memory");
}

template<int OM>
__global__ __launch_bounds__(128, 2)
void gemm_mma(const __nv_bfloat16* __restrict__ Ah, const __nv_bfloat16* __restrict__ Al, int lda,
              const __nv_bfloat16* __restrict__ Bh, const __nv_bfloat16* __restrict__ Bl, int ldb,
              const float* __restrict__ bias, float* __restrict__ C,
              __nv_bfloat16* __restrict__ Ch, __nv_bfloat16* __restrict__ Cl,
              float scale, int ldc, int K)
{
    extern __shared__ char smraw[];
    const uint32_t sb = smem_u32(smraw);
    const int tid = threadIdx.x;
    const int l = tid & 31, w = tid >> 5;
    const int wm = (w >> 1) * 64, wn = (w & 1) * 64;
    const int mb = blockIdx.y * 128, nb = blockIdx.x * 128;
    const int seg = (OM == 3) ? (blockIdx.x >> 3) : 0;
    const int aoff = (OM == 3) ? (seg << 10) : 0;

    const __nv_bfloat16* Ahb = Ah + (size_t)mb * lda + aoff;
    const __nv_bfloat16* Alb = Al + (size_t)mb * lda + aoff;
    const __nv_bfloat16* Bhb = Bh + (size_t)nb * ldb;
    const __nv_bfloat16* Blb = Bl + (size_t)nb * ldb;

    const int rA = l & 15, kselA = l >> 4, swA = (rA >> 1) & 3;
    const uint32_t aRow = (uint32_t)((wm + rA) * 64);
    const uint32_t aK0 = (uint32_t)(((0 + kselA) ^ swA) << 4);
    const uint32_t aK1 = (uint32_t)(((2 + kselA) ^ swA) << 4);
    const int rB = (l & 7) + ((l >> 4) << 3), kselB = (l >> 3) & 1, swB = (rB >> 1) & 3;
    const uint32_t bRow = (uint32_t)((wn + rB) * 64);
    const uint32_t bK0 = (uint32_t)(((0 + kselB) ^ swB) << 4);
    const uint32_t bK1 = (uint32_t)(((2 + kselB) ^ swB) << 4);

    float acc[4][8][4];
#pragma unroll
    for (int mi = 0; mi < 4; mi++)
#pragma unroll
        for (int ni = 0; ni < 8; ni++)
#pragma unroll
            for (int i = 0; i < 4; i++) acc[mi][ni][i] = 0.0f;

    const int NKB = K >> 5;
    issue_stage(sb, 0, 0,  Ahb, Alb, Bhb, Blb, lda, ldb, tid);
    issue_stage(sb, 1, 32, Ahb, Alb, Bhb, Blb, lda, ldb, tid);

    for (int kb = 0; kb < NKB; kb++) {
        if (kb < NKB - 2) asm volatile("cp.async.wait_group 1;" ::: "memory");
        else              asm volatile("cp.async.wait_group 0;" ::: "memory");
        __syncthreads();
        if (kb + 2 < NKB)
            issue_stage(sb, (kb + 2) % 3, (kb + 2) * 32,
                        Ahb, Alb, Bhb, Blb, lda, ldb, tid);

        const uint32_t s = sb + (uint32_t)(kb % 3) * STGB;
#pragma unroll
        for (int kk = 0; kk < 2; kk++) {
            const uint32_t aK = kk ? aK1 : aK0;
            const uint32_t bK = kk ? bK1 : bK0;
            uint32_t ah[4][4], al4[4][4];
#pragma unroll
            for (int mi = 0; mi < 4; mi++) {
                ldsm4(ah[mi],  s +       aRow + mi * 1024 + aK);
                ldsm4(al4[mi], s + OPB + aRow + mi * 1024 + aK);
            }
#pragma unroll
            for (int g = 0; g < 4; g++) {
                uint32_t bh[4], bl[4];
                ldsm4(bh, s + 2 * OPB + bRow + g * 1024 + bK);
                ldsm4(bl, s + 3 * OPB + bRow + g * 1024 + bK);
#pragma unroll
                for (int mi = 0; mi < 4; mi++)
#pragma unroll
                    for (int nk = 0; nk < 2; nk++) {
                        float* c = acc[mi][g * 2 + nk];
                        mma_bf16(c, ah[mi],  &bh[nk * 2]);
                        mma_bf16(c, ah[mi],  &bl[nk * 2]);
                        mma_bf16(c, al4[mi], &bh[nk * 2]);
                    }
            }
        }
    }

    const int cr = l >> 2, cc2 = (l & 3) * 2;

    if (OM == 2) {
        // ---- fused RoPE + split epilogue (GEMM1, q/k tiles only) ----
        __syncthreads();
        float* sE = (float*)smraw;             // 128 x 132 fp32 staging
#pragma unroll
        for (int ni = 0; ni < 8; ni++) {
            const int colg = nb + wn + ni * 8 + cc2;
            const float b0 = bias[colg], b1 = bias[colg + 1];
            const int colL = wn + ni * 8 + cc2;
#pragma unroll
            for (int mi = 0; mi < 4; mi++) {
                const int rowL = wm + mi * 16 + cr;
                sE[rowL * 132 + colL]           = acc[mi][ni][0] + b0;
                sE[rowL * 132 + colL + 1]       = acc[mi][ni][1] + b1;
                sE[(rowL + 8) * 132 + colL]     = acc[mi][ni][2] + b0;
                sE[(rowL + 8) * 132 + colL + 1] = acc[mi][ni][3] + b1;
            }
        }
        __syncthreads();
        const int i0 = (tid & 15) << 1;
        const int hh = (tid >> 4) & 1;
        const int rb0 = tid >> 5;                   // 0..3
        const float invA = (float)exp2(-(double)i0 * 0.41524101186091903);
        const float invB = (float)exp2(-(double)(i0 + 1) * 0.41524101186091903);
        const int colL = hh * 64 + i0;
#pragma unroll 4
        for (int rr = 0; rr < 32; rr++) {
            const int row = rb0 + (rr << 2);
            const float sPos = (float)((mb + row) & (S_LEN - 1));
            float cA, sA, cB, sB;
            sincosf(sPos * invA, &sA, &cA);
            sincosf(sPos * invB, &sB, &cB);
            float2 x0 = *(float2*)&sE[row * 132 + colL];
            float2 x1 = *(float2*)&sE[row * 132 + colL + 32];
            float r00 = x0.x * cA - x1.x * sA, r01 = x0.y * cB - x1.y * sB;
            float r10 = x1.x * cA + x0.x * sA, r11 = x1.y * cB + x0.y * sB;
            uint32_t h0, l0, h1, l1;
            split2(r00, r01, h0, l0);
            split2(r10, r11, h1, l1);
            const size_t base = (size_t)(mb + row) * ldc + nb + colL;
            *(uint32_t*)(Ch + base)      = h0;
            *(uint32_t*)(Cl + base)      = l0;
            *(uint32_t*)(Ch + base + 32) = h1;
            *(uint32_t*)(Cl + base + 32) = l1;
        }
        return;
    }

    if (OM == 3) {
        // ---- merged q2/k2 epilogue: route by segment (0 -> q scaled, 1 -> k) ----
        __nv_bfloat16* Coh = (seg == 0) ? g_qh : g_kh;
        __nv_bfloat16* Col = (seg == 0) ? g_ql : g_kl;
        const float sc = (seg == 0) ? 0.125f : 1.0f;
        const int nbo = nb - (seg << 10);
#pragma unroll
        for (int ni = 0; ni < 8; ni++) {
            const int colg = nb + wn + ni * 8 + cc2;
            const float b0 = bias[colg], b1 = bias[colg + 1];
            const int col = nbo + wn + ni * 8 + cc2;
#pragma unroll
            for (int mi = 0; mi < 4; mi++) {
                const int row = mb + wm + mi * 16 + cr;
                float v0 = (acc[mi][ni][0] + b0) * sc, v1 = (acc[mi][ni][1] + b1) * sc;
                float v2 = (acc[mi][ni][2] + b0) * sc, v3 = (acc[mi][ni][3] + b1) * sc;
                uint32_t h0, l0, h1, l1;
                split2(v0, v1, h0, l0);
                split2(v2, v3, h1, l1);
                *(uint32_t*)(Coh + (size_t)row * 1024 + col) = h0;
                *(uint32_t*)(Col + (size_t)row * 1024 + col) = l0;
                *(uint32_t*)(Coh + (size_t)(row + 8) * 1024 + col) = h1;
                *(uint32_t*)(Col + (size_t)(row + 8) * 1024 + col) = l1;
            }
        }
        return;
    }

    if (OM == 1) {
        // ---- generic bf16 hi/lo split output ----
#pragma unroll
        for (int ni = 0; ni < 8; ni++) {
            const int col = nb + wn + ni * 8 + cc2;
            const float b0 = bias[col], b1 = bias[col + 1];
#pragma unroll
            for (int mi = 0; mi < 4; mi++) {
                const int row = mb + wm + mi * 16 + cr;
                float v0 = (acc[mi][ni][0] + b0) * scale, v1 = (acc[mi][ni][1] + b1) * scale;
                float v2 = (acc[mi][ni][2] + b0) * scale, v3 = (acc[mi][ni][3] + b1) * scale;
                uint32_t h0, l0, h1, l1;
                split2(v0, v1, h0, l0);
                split2(v2, v3, h1, l1);
                *(uint32_t*)(Ch + (size_t)row * ldc + col) = h0;
                *(uint32_t*)(Cl + (size_t)row * ldc + col) = l0;
                *(uint32_t*)(Ch + (size_t)(row + 8) * ldc + col) = h1;
                *(uint32_t*)(Cl + (size_t)(row + 8) * ldc + col) = l1;
            }
        }
        return;
    }

    // OM == 0: fp32 out
#pragma unroll
    for (int ni = 0; ni < 8; ni++) {
        const int col = nb + wn + ni * 8 + cc2;
        const float b0 = bias[col], b1 = bias[col + 1];
#pragma unroll
        for (int mi = 0; mi < 4; mi++) {
            const int row = mb + wm + mi * 16 + cr;
            *(float2*)(C + (size_t)row * ldc + col) =
                make_float2(acc[mi][ni][0] + b0, acc[mi][ni][1] + b1);
            *(float2*)(C + (size_t)(row + 8) * ldc + col) =
                make_float2(acc[mi][ni][2] + b0, acc[mi][ni][3] + b1);
        }
    }
}

// ---------------- Flash attention on mma.sync bf16x2 (R12 proven, 2 CTAs/SM) ----------------
#define ATT_QL   8192
#define ATT_MASK 16384
#define ATT_KV   18432
#define ATT_STG  32768
#define ATT_SMEM (ATT_KV + 2 * ATT_STG)   // 83968
#define NITER    32

__global__ __launch_bounds__(128, 2)
void attn_mma(const __nv_bfloat16* __restrict__ qh, const __nv_bfloat16* __restrict__ ql,
              const __nv_bfloat16* __restrict__ kh, const __nv_bfloat16* __restrict__ kl,
              const __nv_bfloat16* __restrict__ vh, const __nv_bfloat16* __restrict__ vl,
              const unsigned char* __restrict__ maskg,
              __nv_bfloat16* __restrict__ Oh, __nv_bfloat16* __restrict__ Ol)
{
    extern __shared__ char sm[];
    const uint32_t sb = smem_u32(sm);
    const int tid = threadIdx.x, l = tid & 31, w = tid >> 5;
    const int b = blockIdx.z, h = blockIdx.y, q0 = blockIdx.x << 6;
    const size_t rowbase = (size_t)b * S_LEN;
    const int h64 = h << 6;

    {
        const int tile = tid >> 6;
        const __nv_bfloat16* src = tile ? ql : qh;
        const uint32_t dstb = sb + tile * ATT_QL;
        const int base = tid & 63;
#pragma unroll
        for (int i = 0; i < 8; i++) {
            int idx = base + i * 64; int r = idx >> 3, c = idx & 7;
            cp16(dstb + r * 128 + ((c ^ (r & 7)) << 4),
                 src + (rowbase + q0 + r) * 1024 + h64 + c * 8);
        }
        cp16(sb + ATT_MASK + tid * 16, maskg + (size_t)b * S_LEN + tid * 16);
    }
    const int kvtile = tid >> 5;
    const __nv_bfloat16* kvsrc = (kvtile == 0) ? kh : (kvtile == 1) ? kl : (kvtile == 2) ? vh : vl;
    const int kvbase = tid & 31;
#define LOAD_KV(stg, kb) do {                                                     \
        uint32_t dstb = sb + ATT_KV + (stg) * ATT_STG + kvtile * 8192;            \
        _Pragma("unroll")                                                         \
        for (int i = 0; i < 16; i++) {                                            \
            int idx = kvbase + i * 32; int r = idx >> 3, c = idx & 7;             \
            cp16(dstb + r * 128 + ((c ^ (r & 7)) << 4),                           \
                 kvsrc + (rowbase + (kb) + r) * 1024 + h64 + c * 8);              \
        }                                                                         \
        asm volatile("cp.async.commit_group;" ::: "memory");                      \
    } while (0)

    LOAD_KV(0, 0);
    LOAD_KV(1, 64);

    asm volatile("cp.async.wait_group 1;" ::: "memory");
    __syncthreads();

    uint32_t qfh[4][4], qfl[4][4];
    {
        int row = (w << 4) + (l & 15);
#pragma unroll
        for (int j = 0; j < 4; j++) {
            uint32_t ch = (uint32_t)(((2 * j + (l >> 4)) ^ (row & 7)) << 4);
            ldsm4(qfh[j], sb +          row * 128 + ch);
            ldsm4(qfl[j], sb + ATT_QL + row * 128 + ch);
        }
    }

    float o[8][4];
#pragma unroll
    for (int di = 0; di < 8; di++)
#pragma unroll
        for (int i = 0; i < 4; i++) o[di][i] = 0.0f;
    float m0 = -1e30f, m1 = -1e30f, l0 = 0.0f, l1 = 0.0f;

    const unsigned char* Ms = (const unsigned char*)sm + ATT_MASK;

    for (int kt = 0; kt < NITER; kt++) {
        if (kt > 0) {
            if (kt < 30) asm volatile("cp.async.wait_group 1;" ::: "memory");
            else         asm volatile("cp.async.wait_group 0;" ::: "memory");
            __syncthreads();
        }
        const uint32_t stg = sb + ATT_KV + (uint32_t)(kt & 1) * ATT_STG;
        const int kb = kt << 6;

        float S[8][4];
#pragma unroll
        for (int ni = 0; ni < 8; ni++)
#pragma unroll
            for (int i = 0; i < 4; i++) S[ni][i] = 0.0f;

#pragma unroll
        for (int j = 0; j < 4; j++) {
            uint32_t bh4[4][4], bl4[4][4];
#pragma unroll
            for (int ng = 0; ng < 4; ng++) {
                int row = (ng << 4) + (l & 7) + ((l >> 4) << 3);
                uint32_t ch = (uint32_t)(((2 * j + ((l >> 3) & 1)) ^ (row & 7)) << 4);
                ldsm4(bh4[ng], stg +        row * 128 + ch);
                ldsm4(bl4[ng], stg + 8192 + row * 128 + ch);
            }
#pragma unroll
            for (int ni = 0; ni < 8; ni++) {
                uint32_t* bp = &bh4[ni >> 1][(ni & 1) * 2];
                uint32_t* lp = &bl4[ni >> 1][(ni & 1) * 2];
                mma_bf16(S[ni], qfh[j], bp);
                mma_bf16(S[ni], qfh[j], lp);
                mma_bf16(S[ni], qfl[j], bp);
            }
        }

        float tm0 = -1e30f, tm1 = -1e30f;
#pragma unroll
        for (int ni = 0; ni < 8; ni++) {
            uchar2 mm = *(const uchar2*)(Ms + kb + (ni << 3) + ((l & 3) << 1));
            if (mm.x) { S[ni][0] = -1e30f; S[ni][2] = -1e30f; }
            if (mm.y) { S[ni][1] = -1e30f; S[ni][3] = -1e30f; }
            tm0 = fmaxf(tm0, fmaxf(S[ni][0], S[ni][1]));
            tm1 = fmaxf(tm1, fmaxf(S[ni][2], S[ni][3]));
        }
        tm0 = fmaxf(tm0, __shfl_xor_sync(0xffffffffu, tm0, 1));
        tm0 = fmaxf(tm0, __shfl_xor_sync(0xffffffffu, tm0, 2));
        tm1 = fmaxf(tm1, __shfl_xor_sync(0xffffffffu, tm1, 1));
        tm1 = fmaxf(tm1, __shfl_xor_sync(0xffffffffu, tm1, 2));
        float mn0 = fmaxf(m0, tm0), mn1 = fmaxf(m1, tm1);
        float c0 = __expf(m0 - mn0), c1 = __expf(m1 - mn1);
        m0 = mn0; m1 = mn1;
        float rs0 = 0.0f, rs1 = 0.0f;
#pragma unroll
        for (int ni = 0; ni < 8; ni++) {
            S[ni][0] = __expf(S[ni][0] - mn0); rs0 += S[ni][0];
            S[ni][1] = __expf(S[ni][1] - mn0); rs0 += S[ni][1];
            S[ni][2] = __expf(S[ni][2] - mn1); rs1 += S[ni][2];
            S[ni][3] = __expf(S[ni][3] - mn1); rs1 += S[ni][3];
        }
        rs0 += __shfl_xor_sync(0xffffffffu, rs0, 1);
        rs0 += __shfl_xor_sync(0xffffffffu, rs0, 2);
        rs1 += __shfl_xor_sync(0xffffffffu, rs1, 1);
        rs1 += __shfl_xor_sync(0xffffffffu, rs1, 2);
        l0 = l0 * c0 + rs0; l1 = l1 * c1 + rs1;
#pragma unroll
        for (int di = 0; di < 8; di++) {
            o[di][0] *= c0; o[di][1] *= c0; o[di][2] *= c1; o[di][3] *= c1;
        }

#pragma unroll
        for (int js = 0; js < 4; js++) {
            uint32_t pha[4], pla[4];
            {
                const int t0 = 2 * js, t1 = t0 + 1;
                split2(S[t0][0], S[t0][1], pha[0], pla[0]);
                split2(S[t0][2], S[t0][3], pha[1], pla[1]);
                split2(S[t1][0], S[t1][1], pha[2], pla[2]);
                split2(S[t1][2], S[t1][3], pha[3], pla[3]);
            }
            uint32_t vh4[4][4], vl4[4][4];
#pragma unroll
            for (int dg = 0; dg < 4; dg++) {
                int row = (js << 4) + (l & 7) + (((l >> 3) & 1) << 3);
                uint32_t ch = (uint32_t)(((2 * dg + (l >> 4)) ^ (row & 7)) << 4);
                ldsm4t(vh4[dg], stg + 16384 + row * 128 + ch);
                ldsm4t(vl4[dg], stg + 24576 + row * 128 + ch);
            }
#pragma unroll
            for (int di = 0; di < 8; di++) {
                uint32_t* vp = &vh4[di >> 1][(di & 1) * 2];
                uint32_t* lp = &vl4[di >> 1][(di & 1) * 2];
                mma_bf16(o[di], pha, vp);
                mma_bf16(o[di], pha, lp);
                mma_bf16(o[di], pla, vp);
            }
        }

        __syncthreads();
        if (kt + 2 < NITER) LOAD_KV(kt & 1, (kt + 2) << 6);
    }

    const float inv0 = 1.0f / l0, inv1 = 1.0f / l1;
    const int r0 = q0 + (w << 4) + (l >> 2);
#pragma unroll
    for (int di = 0; di < 8; di++) {
        const int col = h64 + (di << 3) + ((l & 3) << 1);
        uint32_t h0, lo0, h1, lo1;
        split2(o[di][0] * inv0, o[di][1] * inv0, h0, lo0);
        split2(o[di][2] * inv1, o[di][3] * inv1, h1, lo1);
        *(uint32_t*)(Oh + (rowbase + r0) * 1024 + col) = h0;
        *(uint32_t*)(Ol + (rowbase + r0) * 1024 + col) = lo0;
        *(uint32_t*)(Oh + (rowbase + r0 + 8) * 1024 + col) = h1;
        *(uint32_t*)(Ol + (rowbase + r0 + 8) * 1024 + col) = lo1;
    }
}

// ---------------- launch ----------------
extern "C" void kernel_launch(void* const* d_in, const int* in_sizes, int n_in,
                              void* d_out, int out_size)
{
    const float* x     = (const float*)d_in[0];
    const float* w_in  = (const float*)d_in[1];
    const float* b_in  = (const float*)d_in[2];
    const float* w_out = (const float*)d_in[3];
    const float* b_out = (const float*)d_in[4];
    const unsigned char* mask = (const unsigned char*)d_in[5];
    float* out = (float*)d_out;

    __nv_bfloat16 *xh, *xl, *wih, *wil, *woh, *wol, *qkh, *qkl;
    __nv_bfloat16 *qh, *ql, *kh, *kl, *vh, *vl, *cth, *ctl;
    __nv_bfloat16 *wvth, *wvtl, *wvvh, *wvvl;
    float *bvv, *zb;
    cudaGetSymbolAddress((void**)&xh,  g_xh);  cudaGetSymbolAddress((void**)&xl,  g_xl);
    cudaGetSymbolAddress((void**)&wih, g_wih); cudaGetSymbolAddress((void**)&wil, g_wil);
    cudaGetSymbolAddress((void**)&woh, g_woh); cudaGetSymbolAddress((void**)&wol, g_wol);
    cudaGetSymbolAddress((void**)&qkh, g_qkh); cudaGetSymbolAddress((void**)&qkl, g_qkl);
    cudaGetSymbolAddress((void**)&qh,  g_qh);  cudaGetSymbolAddress((void**)&ql,  g_ql);
    cudaGetSymbolAddress((void**)&kh,  g_kh);  cudaGetSymbolAddress((void**)&kl,  g_kl);
    cudaGetSymbolAddress((void**)&vh,  g_vh);  cudaGetSymbolAddress((void**)&vl,  g_vl);
    cudaGetSymbolAddress((void**)&cth, g_cth); cudaGetSymbolAddress((void**)&ctl, g_ctl);
    cudaGetSymbolAddress((void**)&wvth, g_wvth); cudaGetSymbolAddress((void**)&wvtl, g_wvtl);
    cudaGetSymbolAddress((void**)&wvvh, g_wvvh); cudaGetSymbolAddress((void**)&wvvl, g_wvvl);
    cudaGetSymbolAddress((void**)&bvv, g_bvv); cudaGetSymbolAddress((void**)&zb, g_zb);

    cudaFuncSetAttribute(gemm_mma<0>, cudaFuncAttributeMaxDynamicSharedMemorySize, GEMM_SMEM);
    cudaFuncSetAttribute(gemm_mma<1>, cudaFuncAttributeMaxDynamicSharedMemorySize, GEMM_SMEM);
    cudaFuncSetAttribute(gemm_mma<2>, cudaFuncAttributeMaxDynamicSharedMemorySize, GEMM_SMEM);
    cudaFuncSetAttribute(gemm_mma<3>, cudaFuncAttributeMaxDynamicSharedMemorySize, GEMM_SMEM);
    cudaFuncSetAttribute(attn_mma,    cudaFuncAttributeMaxDynamicSharedMemorySize, ATT_SMEM);

    const float* Wv = w_in + (size_t)2048 * 1024;   // rows 2048:3072
    const float* bv = b_in + 2048;

    // split inputs
    split_kernel<<<8192, 256>>>(x,     xh,  xl,  2097152);
    split_kernel<<<3072, 256>>>(w_in,  wih, wil, 786432);
    split_kernel<<<1024, 256>>>(w_out, woh, wol, 262144);

    // V-path weight folding: Wvv = Wv@Wv, bvv = Wv@bv + bv
    transpose_split_kernel<<<dim3(32, 32), dim3(32, 8)>>>(Wv, wvth, wvtl);
    bvv_kernel<<<1024, 256>>>(Wv, bv, bvv);
    gemm_mma<1><<<dim3(8, 8), 128, GEMM_SMEM>>>(wih + 2048 * 1024, wil + 2048 * 1024, 1024,
                                                wvth, wvtl, 1024, zb, nullptr,
                                                wvvh, wvvl, 1.0f, 1024, 1024);

    // 1) q,k = x @ W_{q,k}^T + b with fused RoPE + split -> qkh/qkl (8192 x 2048 bf16)
    gemm_mma<2><<<dim3(16, 64), 128, GEMM_SMEM>>>(xh, xl, 1024, wih, wil, 1024,
                                                  b_in, nullptr, qkh, qkl, 1.0f, 2048, 1024);
    // 2) second projection of q,k -> qh/ql (x0.125), kh/kl
    gemm_mma<3><<<dim3(16, 64), 128, GEMM_SMEM>>>(qkh, qkl, 2048, wih, wil, 1024,
                                                  b_in, nullptr, nullptr, nullptr, 1.0f, 1024, 1024);
    // 2b) v2 = x @ Wvv^T + bvv directly (folded projection)
    gemm_mma<1><<<dim3(8, 64), 128, GEMM_SMEM>>>(xh, xl, 1024, wvvh, wvvl, 1024,
                                                 bvv, nullptr, vh, vl, 1.0f, 1024, 1024);
    // 3) attention (2 CTAs/SM) -> ctx hi/lo
    attn_mma<<<dim3(32, 16, 4), 128, ATT_SMEM>>>(qh, ql, kh, kl, vh, vl, mask, cth, ctl);
    // 4) out = ctx @ Wout^T + b (fp32 out)
    gemm_mma<0><<<dim3(8, 64), 128, GEMM_SMEM>>>(cth, ctl, 1024, woh, wol, 1024,
                                                 b_out, out, nullptr, nullptr, 1.0f, 1024, 1024);
}

// round 16
// speedup vs baseline: 1.2080x; 1.0124x over previous
#include <cuda_runtime.h>
#include <cuda_bf16.h>
#include <math.h>
#include <stdint.h>

#define E_DIM 1024
#define S_LEN 2048

// ---------------- scratch (no allocation allowed) ----------------
__device__ __nv_bfloat16 g_xh [8388608],  g_xl [8388608];
__device__ __nv_bfloat16 g_wih[3145728],  g_wil[3145728];
__device__ __nv_bfloat16 g_woh[1048576],  g_wol[1048576];
__device__ __nv_bfloat16 g_qkh[25165824], g_qkl[25165824];  // rope'd q,k hi/lo (8192x2048)
__device__ __nv_bfloat16 g_qh [8388608],  g_ql [8388608];   // q2 hi/lo (scaled 0.125)
__device__ __nv_bfloat16 g_kh [8388608],  g_kl [8388608];
__device__ __nv_bfloat16 g_vh [8388608],  g_vl [8388608];
__device__ __nv_bfloat16 g_cth[8388608],  g_ctl[8388608];   // ctx hi/lo
__device__ __nv_bfloat16 g_wvth[1048576], g_wvtl[1048576];  // Wv^T hi/lo
__device__ __nv_bfloat16 g_wvvh[1048576], g_wvvl[1048576];  // Wvv = Wv@Wv hi/lo
__device__ float g_bvv[1024];                               // Wv@bv + bv
__device__ float g_zb [1024];                               // zeros (never written)

// ---------------- helpers ----------------
__device__ __forceinline__ uint32_t smem_u32(const void* p) {
    uint32_t a;
    asm("{ .reg .u64 t; cvta.to.shared.u64 t, %1; cvt.u32.u64 %0, t; }" : "=r"(a) : "l"(p));
    return a;
}
__device__ __forceinline__ void cp16(uint32_t s, const void* g) {
    asm volatile("cp.async.cg.shared.global [%0], [%1], 16;" :: "r"(s), "l"(g));
}
__device__ __forceinline__ void ldsm4(uint32_t* r, uint32_t a) {
    asm volatile("ldmatrix.sync.aligned.m8n8.x4.shared.b16 {%0,%1,%2,%3}, [%4];"
        : "=r"(r[0]), "=r"(r[1]), "=r"(r[2]), "=r"(r[3]) : "r"(a));
}
__device__ __forceinline__ void ldsm4t(uint32_t* r, uint32_t a) {
    asm volatile("ldmatrix.sync.aligned.m8n8.x4.trans.shared.b16 {%0,%1,%2,%3}, [%4];"
        : "=r"(r[0]), "=r"(r[1]), "=r"(r[2]), "=r"(r[3]) : "r"(a));
}
__device__ __forceinline__ void mma_bf16(float* c, const uint32_t* a, const uint32_t* b) {
    asm volatile("mma.sync.aligned.m16n8k16.row.col.f32.bf16.bf16.f32 "
        "{%0,%1,%2,%3}, {%4,%5,%6,%7}, {%8,%9}, {%0,%1,%2,%3};"
        : "+f"(c[0]), "+f"(c[1]), "+f"(c[2]), "+f"(c[3])
        : "r"(a[0]), "r"(a[1]), "r"(a[2]), "r"(a[3]), "r"(b[0]), "r"(b[1]));
}
__device__ __forceinline__ uint32_t pack2(__nv_bfloat16 a, __nv_bfloat16 b) {
    unsigned short ua = *(unsigned short*)&a, ub = *(unsigned short*)&b;
    return (uint32_t)ua | ((uint32_t)ub << 16);
}
__device__ __forceinline__ void split2(float x, float y, uint32_t& hi, uint32_t& lo) {
    __nv_bfloat16 hx = __float2bfloat16_rn(x);
    __nv_bfloat16 hy = __float2bfloat16_rn(y);
    __nv_bfloat16 lx = __float2bfloat16_rn(x - __bfloat162float(hx));
    __nv_bfloat16 ly = __float2bfloat16_rn(y - __bfloat162float(hy));
    hi = pack2(hx, hy); lo = pack2(lx, ly);
}

// ---------------- split fp32 -> bf16 hi + bf16 lo ----------------
__global__ void split_kernel(const float* __restrict__ src,
                             __nv_bfloat16* __restrict__ hi,
                             __nv_bfloat16* __restrict__ lo, int n4)
{
    int q = blockIdx.x * 256 + threadIdx.x;
    if (q >= n4) return;
    int i = q << 2;
    float4 v = *(const float4*)(src + i);
    uint32_t h0, l0, h1, l1;
    split2(v.x, v.y, h0, l0);
    split2(v.z, v.w, h1, l1);
    *(uint32_t*)(hi + i)     = h0;  *(uint32_t*)(hi + i + 2) = h1;
    *(uint32_t*)(lo + i)     = l0;  *(uint32_t*)(lo + i + 2) = l1;
}

// ---------------- transpose + split: dst[n][k] = src[k][n] (1024x1024 fp32) ----------------
__global__ void transpose_split_kernel(const float* __restrict__ src,
                                       __nv_bfloat16* __restrict__ th,
                                       __nv_bfloat16* __restrict__ tl)
{
    __shared__ float t[32][33];
    const int bx = blockIdx.x << 5, by = blockIdx.y << 5;
    const int x = threadIdx.x;
#pragma unroll
    for (int j = threadIdx.y; j < 32; j += 8)
        t[j][x] = src[(size_t)(by + j) * 1024 + bx + x];
    __syncthreads();
#pragma unroll
    for (int j = threadIdx.y; j < 32; j += 8) {
        float v = t[x][j];
        __nv_bfloat16 h = __float2bfloat16_rn(v);
        __nv_bfloat16 l = __float2bfloat16_rn(v - __bfloat162float(h));
        const size_t o = (size_t)(bx + j) * 1024 + by + x;
        th[o] = h; tl[o] = l;
    }
}

// ---------------- bvv[i] = bv[i] + sum_k Wv[i][k]*bv[k] ----------------
__global__ void bvv_kernel(const float* __restrict__ Wv, const float* __restrict__ bv,
                           float* __restrict__ bvv)
{
    __shared__ float red[8];
    const int row = blockIdx.x;
    float s = 0.0f;
    for (int k = threadIdx.x; k < 1024; k += 256)
        s += Wv[(size_t)row * 1024 + k] * bv[k];
#pragma unroll
    for (int off = 16; off; off >>= 1) s += __shfl_xor_sync(0xffffffffu, s, off);
    if ((threadIdx.x & 31) == 0) red[threadIdx.x >> 5] = s;
    __syncthreads();
    if (threadIdx.x == 0) {
        float t = 0.0f;
#pragma unroll
        for (int i = 0; i < 8; i++) t += red[i];
        bvv[row] = t + bv[row];
    }
}

// ---------------- mma.sync bf16x2 GEMM: C = A @ B^T + bias ----------------
// 128 threads, 4 warps @ 64x64, CTA 128x128, 3-stage pipeline.
// OM=0: fp32 out.  OM=1: bf16 hi/lo out to Ch/Cl (scale after bias).
// OM=2: MERGED GEMM1: tiles 0..15 = q,k with RoPE epilogue -> Ch/Cl (ldc=2048);
//       tiles 16..23 = v-direct (B := g_wvv, bias := g_bvv) -> g_vh/g_vl.
// OM=3: q/k second projection routed out (seg = blockIdx.x>>3 in {0,1}).
#define OPB       8192
#define STGB      (4 * OPB)
#define GEMM_SMEM (3 * STGB)

__device__ __forceinline__ void issue_stage(uint32_t sb, int stg, int k0,
    const __nv_bfloat16* Ahb, const __nv_bfloat16* Alb,
    const __nv_bfloat16* Bhb, const __nv_bfloat16* Blb,
    int lda, int ldb, int tid)
{
    uint32_t s = sb + (uint32_t)stg * STGB;
    const int c = tid & 3;
    const int r0 = tid >> 2;               // 0..31
    const int kb8 = k0 + c * 8;
#pragma unroll
    for (int i = 0; i < 4; i++) {
        const int r = r0 + i * 32;
        const uint32_t so = (uint32_t)(r * 64 + ((c ^ ((r >> 1) & 3)) << 4));
        cp16(s +           so, Ahb + (size_t)r * lda + kb8);
        cp16(s + OPB +     so, Alb + (size_t)r * lda + kb8);
        cp16(s + 2 * OPB + so, Bhb + (size_t)r * ldb + kb8);
        cp16(s + 3 * OPB + so, Blb + (size_t)r * ldb + kb8);
    }
    asm volatile("cp.async.commit_group;" ::: "memory");
}

template<int OM>
__global__ __launch_bounds__(128, 2)
void gemm_mma(const __nv_bfloat16* __restrict__ Ah, const __nv_bfloat16* __restrict__ Al, int lda,
              const __nv_bfloat16* __restrict__ Bh, const __nv_bfloat16* __restrict__ Bl, int ldb,
              const float* __restrict__ bias, float* __restrict__ C,
              __nv_bfloat16* __restrict__ Ch, __nv_bfloat16* __restrict__ Cl,
              float scale, int ldc, int K)
{
    extern __shared__ char smraw[];
    const uint32_t sb = smem_u32(smraw);
    const int tid = threadIdx.x;
    const int l = tid & 31, w = tid >> 5;
    const int wm = (w >> 1) * 64, wn = (w & 1) * 64;
    const int mb = blockIdx.y * 128, nb = blockIdx.x * 128;
    const int seg = (OM == 3) ? (blockIdx.x >> 3) : 0;
    const int aoff = (OM == 3) ? (seg << 10) : 0;
    const bool vtile = (OM == 2) && (blockIdx.x >= 16);   // merged v-direct tiles

    const __nv_bfloat16* Ahb = Ah + (size_t)mb * lda + aoff;
    const __nv_bfloat16* Alb = Al + (size_t)mb * lda + aoff;
    const __nv_bfloat16* Bhb;
    const __nv_bfloat16* Blb;
    if (vtile) {
        const int nbv = nb - 2048;
        Bhb = g_wvvh + (size_t)nbv * ldb;
        Blb = g_wvvl + (size_t)nbv * ldb;
    } else {
        Bhb = Bh + (size_t)nb * ldb;
        Blb = Bl + (size_t)nb * ldb;
    }

    const int rA = l & 15, kselA = l >> 4, swA = (rA >> 1) & 3;
    const uint32_t aRow = (uint32_t)((wm + rA) * 64);
    const uint32_t aK0 = (uint32_t)(((0 + kselA) ^ swA) << 4);
    const uint32_t aK1 = (uint32_t)(((2 + kselA) ^ swA) << 4);
    const int rB = (l & 7) + ((l >> 4) << 3), kselB = (l >> 3) & 1, swB = (rB >> 1) & 3;
    const uint32_t bRow = (uint32_t)((wn + rB) * 64);
    const uint32_t bK0 = (uint32_t)(((0 + kselB) ^ swB) << 4);
    const uint32_t bK1 = (uint32_t)(((2 + kselB) ^ swB) << 4);

    float acc[4][8][4];
#pragma unroll
    for (int mi = 0; mi < 4; mi++)
#pragma unroll
        for (int ni = 0; ni < 8; ni++)
#pragma unroll
            for (int i = 0; i < 4; i++) acc[mi][ni][i] = 0.0f;

    const int NKB = K >> 5;
    issue_stage(sb, 0, 0,  Ahb, Alb, Bhb, Blb, lda, ldb, tid);
    issue_stage(sb, 1, 32, Ahb, Alb, Bhb, Blb, lda, ldb, tid);

    for (int kb = 0; kb < NKB; kb++) {
        if (kb < NKB - 2) asm volatile("cp.async.wait_group 1;" ::: "memory");
        else              asm volatile("cp.async.wait_group 0;" ::: "memory");
        __syncthreads();
        if (kb + 2 < NKB)
            issue_stage(sb, (kb + 2) % 3, (kb + 2) * 32,
                        Ahb, Alb, Bhb, Blb, lda, ldb, tid);

        const uint32_t s = sb + (uint32_t)(kb % 3) * STGB;
#pragma unroll
        for (int kk = 0; kk < 2; kk++) {
            const uint32_t aK = kk ? aK1 : aK0;
            const uint32_t bK = kk ? bK1 : bK0;
            uint32_t ah[4][4], al4[4][4];
#pragma unroll
            for (int mi = 0; mi < 4; mi++) {
                ldsm4(ah[mi],  s +       aRow + mi * 1024 + aK);
                ldsm4(al4[mi], s + OPB + aRow + mi * 1024 + aK);
            }
#pragma unroll
            for (int g = 0; g < 4; g++) {
                uint32_t bh[4], bl[4];
                ldsm4(bh, s + 2 * OPB + bRow + g * 1024 + bK);
                ldsm4(bl, s + 3 * OPB + bRow + g * 1024 + bK);
#pragma unroll
                for (int mi = 0; mi < 4; mi++)
#pragma unroll
                    for (int nk = 0; nk < 2; nk++) {
                        float* c = acc[mi][g * 2 + nk];
                        mma_bf16(c, ah[mi],  &bh[nk * 2]);
                        mma_bf16(c, ah[mi],  &bl[nk * 2]);
                        mma_bf16(c, al4[mi], &bh[nk * 2]);
                    }
            }
        }
    }

    const int cr = l >> 2, cc2 = (l & 3) * 2;

    if (OM == 2) {
        if (vtile) {
            // ---- v-direct epilogue: bf16 hi/lo to g_vh/g_vl, bias g_bvv ----
            const int nbv = nb - 2048;
#pragma unroll
            for (int ni = 0; ni < 8; ni++) {
                const int col = nbv + wn + ni * 8 + cc2;
                const float b0 = g_bvv[col], b1 = g_bvv[col + 1];
#pragma unroll
                for (int mi = 0; mi < 4; mi++) {
                    const int row = mb + wm + mi * 16 + cr;
                    float v0 = acc[mi][ni][0] + b0, v1 = acc[mi][ni][1] + b1;
                    float v2 = acc[mi][ni][2] + b0, v3 = acc[mi][ni][3] + b1;
                    uint32_t h0, l0, h1, l1;
                    split2(v0, v1, h0, l0);
                    split2(v2, v3, h1, l1);
                    *(uint32_t*)(g_vh + (size_t)row * 1024 + col) = h0;
                    *(uint32_t*)(g_vl + (size_t)row * 1024 + col) = l0;
                    *(uint32_t*)(g_vh + (size_t)(row + 8) * 1024 + col) = h1;
                    *(uint32_t*)(g_vl + (size_t)(row + 8) * 1024 + col) = l1;
                }
            }
            return;
        }
        // ---- fused RoPE + split epilogue (q/k tiles) ----
        __syncthreads();
        float* sE = (float*)smraw;             // 128 x 132 fp32 staging
#pragma unroll
        for (int ni = 0; ni < 8; ni++) {
            const int colg = nb + wn + ni * 8 + cc2;
            const float b0 = bias[colg], b1 = bias[colg + 1];
            const int colL = wn + ni * 8 + cc2;
#pragma unroll
            for (int mi = 0; mi < 4; mi++) {
                const int rowL = wm + mi * 16 + cr;
                sE[rowL * 132 + colL]           = acc[mi][ni][0] + b0;
                sE[rowL * 132 + colL + 1]       = acc[mi][ni][1] + b1;
                sE[(rowL + 8) * 132 + colL]     = acc[mi][ni][2] + b0;
                sE[(rowL + 8) * 132 + colL + 1] = acc[mi][ni][3] + b1;
            }
        }
        __syncthreads();
        const int i0 = (tid & 15) << 1;
        const int hh = (tid >> 4) & 1;
        const int rb0 = tid >> 5;                   // 0..3
        const float invA = (float)exp2(-(double)i0 * 0.41524101186091903);
        const float invB = (float)exp2(-(double)(i0 + 1) * 0.41524101186091903);
        const int colL = hh * 64 + i0;
#pragma unroll 4
        for (int rr = 0; rr < 32; rr++) {
            const int row = rb0 + (rr << 2);
            const float sPos = (float)((mb + row) & (S_LEN - 1));
            float cA, sA, cB, sB;
            sincosf(sPos * invA, &sA, &cA);
            sincosf(sPos * invB, &sB, &cB);
            float2 x0 = *(float2*)&sE[row * 132 + colL];
            float2 x1 = *(float2*)&sE[row * 132 + colL + 32];
            float r00 = x0.x * cA - x1.x * sA, r01 = x0.y * cB - x1.y * sB;
            float r10 = x1.x * cA + x0.x * sA, r11 = x1.y * cB + x0.y * sB;
            uint32_t h0, l0, h1, l1;
            split2(r00, r01, h0, l0);
            split2(r10, r11, h1, l1);
            const size_t base = (size_t)(mb + row) * ldc + nb + colL;
            *(uint32_t*)(Ch + base)      = h0;
            *(uint32_t*)(Cl + base)      = l0;
            *(uint32_t*)(Ch + base + 32) = h1;
            *(uint32_t*)(Cl + base + 32) = l1;
        }
        return;
    }

    if (OM == 3) {
        // ---- merged q2/k2 epilogue: route by segment (0 -> q scaled, 1 -> k) ----
        __nv_bfloat16* Coh = (seg == 0) ? g_qh : g_kh;
        __nv_bfloat16* Col = (seg == 0) ? g_ql : g_kl;
        const float sc = (seg == 0) ? 0.125f : 1.0f;
        const int nbo = nb - (seg << 10);
#pragma unroll
        for (int ni = 0; ni < 8; ni++) {
            const int colg = nb + wn + ni * 8 + cc2;
            const float b0 = bias[colg], b1 = bias[colg + 1];
            const int col = nbo + wn + ni * 8 + cc2;
#pragma unroll
            for (int mi = 0; mi < 4; mi++) {
                const int row = mb + wm + mi * 16 + cr;
                float v0 = (acc[mi][ni][0] + b0) * sc, v1 = (acc[mi][ni][1] + b1) * sc;
                float v2 = (acc[mi][ni][2] + b0) * sc, v3 = (acc[mi][ni][3] + b1) * sc;
                uint32_t h0, l0, h1, l1;
                split2(v0, v1, h0, l0);
                split2(v2, v3, h1, l1);
                *(uint32_t*)(Coh + (size_t)row * 1024 + col) = h0;
                *(uint32_t*)(Col + (size_t)row * 1024 + col) = l0;
                *(uint32_t*)(Coh + (size_t)(row + 8) * 1024 + col) = h1;
                *(uint32_t*)(Col + (size_t)(row + 8) * 1024 + col) = l1;
            }
        }
        return;
    }

    if (OM == 1) {
        // ---- generic bf16 hi/lo split output ----
#pragma unroll
        for (int ni = 0; ni < 8; ni++) {
            const int col = nb + wn + ni * 8 + cc2;
            const float b0 = bias[col], b1 = bias[col + 1];
#pragma unroll
            for (int mi = 0; mi < 4; mi++) {
                const int row = mb + wm + mi * 16 + cr;
                float v0 = (acc[mi][ni][0] + b0) * scale, v1 = (acc[mi][ni][1] + b1) * scale;
                float v2 = (acc[mi][ni][2] + b0) * scale, v3 = (acc[mi][ni][3] + b1) * scale;
                uint32_t h0, l0, h1, l1;
                split2(v0, v1, h0, l0);
                split2(v2, v3, h1, l1);
                *(uint32_t*)(Ch + (size_t)row * ldc + col) = h0;
                *(uint32_t*)(Cl + (size_t)row * ldc + col) = l0;
                *(uint32_t*)(Ch + (size_t)(row + 8) * ldc + col) = h1;
                *(uint32_t*)(Cl + (size_t)(row + 8) * ldc + col) = l1;
            }
        }
        return;
    }

    // OM == 0: fp32 out
#pragma unroll
    for (int ni = 0; ni < 8; ni++) {
        const int col = nb + wn + ni * 8 + cc2;
        const float b0 = bias[col], b1 = bias[col + 1];
#pragma unroll
        for (int mi = 0; mi < 4; mi++) {
            const int row = mb + wm + mi * 16 + cr;
            *(float2*)(C + (size_t)row * ldc + col) =
                make_float2(acc[mi][ni][0] + b0, acc[mi][ni][1] + b1);
            *(float2*)(C + (size_t)(row + 8) * ldc + col) =
                make_float2(acc[mi][ni][2] + b0, acc[mi][ni][3] + b1);
        }
    }
}

// ---------------- Flash attention, bf16 3-pass, 3-stage KV + Q-overlay, 2 CTAs/SM ----------
// 128 threads, 64 q-rows/CTA, 64 k-cols/iter.  Single __syncthreads per iteration:
// load target stage (kt+2)%3 was last read in iter kt-1, already fenced by top barrier.
// smem: mask[0..2K) | 3 x 32K stages at [2K..98.1K).  Q hi/lo staged in stage0 region
// during prologue (dead after fragment load).  Total 100352 B -> 2 CTAs/SM.
#define ATT_MASK 0
#define ATT_KV   2048
#define ATT_STG  32768
#define ATT_SMEM (2048 + 3 * ATT_STG)   // 100352
#define NITER    32

__global__ __launch_bounds__(128, 2)
void attn_mma(const __nv_bfloat16* __restrict__ qh, const __nv_bfloat16* __restrict__ ql,
              const __nv_bfloat16* __restrict__ kh, const __nv_bfloat16* __restrict__ kl,
              const __nv_bfloat16* __restrict__ vh, const __nv_bfloat16* __restrict__ vl,
              const unsigned char* __restrict__ maskg,
              __nv_bfloat16* __restrict__ Oh, __nv_bfloat16* __restrict__ Ol)
{
    extern __shared__ char sm[];
    const uint32_t sb = smem_u32(sm);
    const int tid = threadIdx.x, l = tid & 31, w = tid >> 5;
    const int b = blockIdx.z, h = blockIdx.y, q0 = blockIdx.x << 6;
    const size_t rowbase = (size_t)b * S_LEN;
    const int h64 = h << 6;

    // ---- prologue phase 1: Q hi/lo into stage-0 region + mask ----
    {
        const int tile = tid >> 6;                  // 0: hi, 1: lo
        const __nv_bfloat16* src = tile ? ql : qh;
        const uint32_t dstb = sb + ATT_KV + tile * 8192;
        const int base = tid & 63;
#pragma unroll
        for (int i = 0; i < 8; i++) {
            int idx = base + i * 64; int r = idx >> 3, c = idx & 7;
            cp16(dstb + r * 128 + ((c ^ (r & 7)) << 4),
                 src + (rowbase + q0 + r) * 1024 + h64 + c * 8);
        }
        cp16(sb + ATT_MASK + tid * 16, maskg + (size_t)b * S_LEN + tid * 16);
        asm volatile("cp.async.commit_group;" ::: "memory");
    }
    asm volatile("cp.async.wait_group 0;" ::: "memory");
    __syncthreads();

    // ---- Q fragments (persistent), then release stage-0 smem for KV ----
    uint32_t qfh[4][4], qfl[4][4];
    {
        int row = (w << 4) + (l & 15);
#pragma unroll
        for (int j = 0; j < 4; j++) {
            uint32_t ch = (uint32_t)(((2 * j + (l >> 4)) ^ (row & 7)) << 4);
            ldsm4(qfh[j], sb + ATT_KV +        row * 128 + ch);
            ldsm4(qfl[j], sb + ATT_KV + 8192 + row * 128 + ch);
        }
    }
    __syncthreads();   // all warps done reading Q smem

    // ---- prologue phase 2: KV stages 0, 1 ----
    const int kvtile = tid >> 5;
    const __nv_bfloat16* kvsrc = (kvtile == 0) ? kh : (kvtile == 1) ? kl : (kvtile == 2) ? vh : vl;
    const int kvbase = tid & 31;
#define LOAD_KV(stg, kb) do {                                                     \
        uint32_t dstb = sb + ATT_KV + (stg) * ATT_STG + kvtile * 8192;            \
        _Pragma("unroll")                                                         \
        for (int i = 0; i < 16; i++) {                                            \
            int idx = kvbase + i * 32; int r = idx >> 3, c = idx & 7;             \
            cp16(dstb + r * 128 + ((c ^ (r & 7)) << 4),                           \
                 kvsrc + (rowbase + (kb) + r) * 1024 + h64 + c * 8);              \
        }                                                                         \
        asm volatile("cp.async.commit_group;" ::: "memory");                      \
    } while (0)

    LOAD_KV(0, 0);
    LOAD_KV(1, 64);

    float o[8][4];
#pragma unroll
    for (int di = 0; di < 8; di++)
#pragma unroll
        for (int i = 0; i < 4; i++) o[di][i] = 0.0f;
    float m0 = -1e30f, m1 = -1e30f, l0 = 0.0f, l1 = 0.0f;

    const unsigned char* Ms = (const unsigned char*)sm + ATT_MASK;

    for (int kt = 0; kt < NITER; kt++) {
        if (kt < NITER - 2) asm volatile("cp.async.wait_group 1;" ::: "memory");
        else                asm volatile("cp.async.wait_group 0;" ::: "memory");
        __syncthreads();
        // issue next load immediately (target stage fully consumed at iter kt-1)
        if (kt + 2 < NITER) LOAD_KV((kt + 2) % 3, (kt + 2) << 6);

        const uint32_t stg = sb + ATT_KV + (uint32_t)(kt % 3) * ATT_STG;
        const int kb = kt << 6;

        // ---- S = Q K^T (3-pass split) ----
        float S[8][4];
#pragma unroll
        for (int ni = 0; ni < 8; ni++)
#pragma unroll
            for (int i = 0; i < 4; i++) S[ni][i] = 0.0f;

#pragma unroll
        for (int j = 0; j < 4; j++) {
            uint32_t bh4[4][4], bl4[4][4];
#pragma unroll
            for (int ng = 0; ng < 4; ng++) {
                int row = (ng << 4) + (l & 7) + ((l >> 4) << 3);
                uint32_t ch = (uint32_t)(((2 * j + ((l >> 3) & 1)) ^ (row & 7)) << 4);
                ldsm4(bh4[ng], stg +        row * 128 + ch);
                ldsm4(bl4[ng], stg + 8192 + row * 128 + ch);
            }
#pragma unroll
            for (int ni = 0; ni < 8; ni++) {
                uint32_t* bp = &bh4[ni >> 1][(ni & 1) * 2];
                uint32_t* lp = &bl4[ni >> 1][(ni & 1) * 2];
                mma_bf16(S[ni], qfh[j], bp);
                mma_bf16(S[ni], qfh[j], lp);
                mma_bf16(S[ni], qfl[j], bp);
            }
        }

        // ---- mask + online softmax ----
        float tm0 = -1e30f, tm1 = -1e30f;
#pragma unroll
        for (int ni = 0; ni < 8; ni++) {
            uchar2 mm = *(const uchar2*)(Ms + kb + (ni << 3) + ((l & 3) << 1));
            if (mm.x) { S[ni][0] = -1e30f; S[ni][2] = -1e30f; }
            if (mm.y) { S[ni][1] = -1e30f; S[ni][3] = -1e30f; }
            tm0 = fmaxf(tm0, fmaxf(S[ni][0], S[ni][1]));
            tm1 = fmaxf(tm1, fmaxf(S[ni][2], S[ni][3]));
        }
        tm0 = fmaxf(tm0, __shfl_xor_sync(0xffffffffu, tm0, 1));
        tm0 = fmaxf(tm0, __shfl_xor_sync(0xffffffffu, tm0, 2));
        tm1 = fmaxf(tm1, __shfl_xor_sync(0xffffffffu, tm1, 1));
        tm1 = fmaxf(tm1, __shfl_xor_sync(0xffffffffu, tm1, 2));
        float mn0 = fmaxf(m0, tm0), mn1 = fmaxf(m1, tm1);
        float c0 = __expf(m0 - mn0), c1 = __expf(m1 - mn1);
        m0 = mn0; m1 = mn1;
        float rs0 = 0.0f, rs1 = 0.0f;
#pragma unroll
        for (int ni = 0; ni < 8; ni++) {
            S[ni][0] = __expf(S[ni][0] - mn0); rs0 += S[ni][0];
            S[ni][1] = __expf(S[ni][1] - mn0); rs0 += S[ni][1];
            S[ni][2] = __expf(S[ni][2] - mn1); rs1 += S[ni][2];
            S[ni][3] = __expf(S[ni][3] - mn1); rs1 += S[ni][3];
        }
        rs0 += __shfl_xor_sync(0xffffffffu, rs0, 1);
        rs0 += __shfl_xor_sync(0xffffffffu, rs0, 2);
        rs1 += __shfl_xor_sync(0xffffffffu, rs1, 1);
        rs1 += __shfl_xor_sync(0xffffffffu, rs1, 2);
        l0 = l0 * c0 + rs0; l1 = l1 * c1 + rs1;
#pragma unroll
        for (int di = 0; di < 8; di++) {
            o[di][0] *= c0; o[di][1] *= c0; o[di][2] *= c1; o[di][3] *= c1;
        }

        // ---- O += P V (3-pass split; P in registers) ----
#pragma unroll
        for (int js = 0; js < 4; js++) {
            uint32_t pha[4], pla[4];
            {
                const int t0 = 2 * js, t1 = t0 + 1;
                split2(S[t0][0], S[t0][1], pha[0], pla[0]);
                split2(S[t0][2], S[t0][3], pha[1], pla[1]);
                split2(S[t1][0], S[t1][1], pha[2], pla[2]);
                split2(S[t1][2], S[t1][3], pha[3], pla[3]);
            }
            uint32_t vh4[4][4], vl4[4][4];
#pragma unroll
            for (int dg = 0; dg < 4; dg++) {
                int row = (js << 4) + (l & 7) + (((l >> 3) & 1) << 3);
                uint32_t ch = (uint32_t)(((2 * dg + (l >> 4)) ^ (row & 7)) << 4);
                ldsm4t(vh4[dg], stg + 16384 + row * 128 + ch);
                ldsm4t(vl4[dg], stg + 24576 + row * 128 + ch);
            }
#pragma unroll
            for (int di = 0; di < 8; di++) {
                uint32_t* vp = &vh4[di >> 1][(di & 1) * 2];
                uint32_t* lp = &vl4[di >> 1][(di & 1) * 2];
                mma_bf16(o[di], pha, vp);
                mma_bf16(o[di], pha, lp);
                mma_bf16(o[di], pla, vp);
            }
        }
    }

    // ---- epilogue: normalize, split, store ----
    const float inv0 = 1.0f / l0, inv1 = 1.0f / l1;
    const int r0 = q0 + (w << 4) + (l >> 2);
#pragma unroll
    for (int di = 0; di < 8; di++) {
        const int col = h64 + (di << 3) + ((l & 3) << 1);
        uint32_t h0, lo0, h1, lo1;
        split2(o[di][0] * inv0, o[di][1] * inv0, h0, lo0);
        split2(o[di][2] * inv1, o[di][3] * inv1, h1, lo1);
        *(uint32_t*)(Oh + (rowbase + r0) * 1024 + col) = h0;
        *(uint32_t*)(Ol + (rowbase + r0) * 1024 + col) = lo0;
        *(uint32_t*)(Oh + (rowbase + r0 + 8) * 1024 + col) = h1;
        *(uint32_t*)(Ol + (rowbase + r0 + 8) * 1024 + col) = lo1;
    }
}

// ---------------- launch ----------------
extern "C" void kernel_launch(void* const* d_in, const int* in_sizes, int n_in,
                              void* d_out, int out_size)
{
    const float* x     = (const float*)d_in[0];
    const float* w_in  = (const float*)d_in[1];
    const float* b_in  = (const float*)d_in[2];
    const float* w_out = (const float*)d_in[3];
    const float* b_out = (const float*)d_in[4];
    const unsigned char* mask = (const unsigned char*)d_in[5];
    float* out = (float*)d_out;

    __nv_bfloat16 *xh, *xl, *wih, *wil, *woh, *wol, *qkh, *qkl;
    __nv_bfloat16 *qh, *ql, *kh, *kl, *vh, *vl, *cth, *ctl;
    __nv_bfloat16 *wvth, *wvtl, *wvvh, *wvvl;
    float *bvv, *zb;
    cudaGetSymbolAddress((void**)&xh,  g_xh);  cudaGetSymbolAddress((void**)&xl,  g_xl);
    cudaGetSymbolAddress((void**)&wih, g_wih); cudaGetSymbolAddress((void**)&wil, g_wil);
    cudaGetSymbolAddress((void**)&woh, g_woh); cudaGetSymbolAddress((void**)&wol, g_wol);
    cudaGetSymbolAddress((void**)&qkh, g_qkh); cudaGetSymbolAddress((void**)&qkl, g_qkl);
    cudaGetSymbolAddress((void**)&qh,  g_qh);  cudaGetSymbolAddress((void**)&ql,  g_ql);
    cudaGetSymbolAddress((void**)&kh,  g_kh);  cudaGetSymbolAddress((void**)&kl,  g_kl);
    cudaGetSymbolAddress((void**)&vh,  g_vh);  cudaGetSymbolAddress((void**)&vl,  g_vl);
    cudaGetSymbolAddress((void**)&cth, g_cth); cudaGetSymbolAddress((void**)&ctl, g_ctl);
    cudaGetSymbolAddress((void**)&wvth, g_wvth); cudaGetSymbolAddress((void**)&wvtl, g_wvtl);
    cudaGetSymbolAddress((void**)&wvvh, g_wvvh); cudaGetSymbolAddress((void**)&wvvl, g_wvvl);
    cudaGetSymbolAddress((void**)&bvv, g_bvv); cudaGetSymbolAddress((void**)&zb, g_zb);

    cudaFuncSetAttribute(gemm_mma<0>, cudaFuncAttributeMaxDynamicSharedMemorySize, GEMM_SMEM);
    cudaFuncSetAttribute(gemm_mma<1>, cudaFuncAttributeMaxDynamicSharedMemorySize, GEMM_SMEM);
    cudaFuncSetAttribute(gemm_mma<2>, cudaFuncAttributeMaxDynamicSharedMemorySize, GEMM_SMEM);
    cudaFuncSetAttribute(gemm_mma<3>, cudaFuncAttributeMaxDynamicSharedMemorySize, GEMM_SMEM);
    cudaFuncSetAttribute(attn_mma,    cudaFuncAttributeMaxDynamicSharedMemorySize, ATT_SMEM);

    const float* Wv = w_in + (size_t)2048 * 1024;   // rows 2048:3072
    const float* bv = b_in + 2048;

    // split inputs
    split_kernel<<<8192, 256>>>(x,     xh,  xl,  2097152);
    split_kernel<<<3072, 256>>>(w_in,  wih, wil, 786432);
    split_kernel<<<1024, 256>>>(w_out, woh, wol, 262144);

    // V-path weight folding: Wvv = Wv@Wv, bvv = Wv@bv + bv
    transpose_split_kernel<<<dim3(32, 32), dim3(32, 8)>>>(Wv, wvth, wvtl);
    bvv_kernel<<<1024, 256>>>(Wv, bv, bvv);
    gemm_mma<1><<<dim3(8, 8), 128, GEMM_SMEM>>>(wih + 2048 * 1024, wil + 2048 * 1024, 1024,
                                                wvth, wvtl, 1024, zb, nullptr,
                                                wvvh, wvvl, 1.0f, 1024, 1024);

    // 1) MERGED: tiles 0..15 q,k (RoPE+split -> qkh/qkl) ; tiles 16..23 v-direct -> vh/vl
    gemm_mma<2><<<dim3(24, 64), 128, GEMM_SMEM>>>(xh, xl, 1024, wih, wil, 1024,
                                                  b_in, nullptr, qkh, qkl, 1.0f, 2048, 1024);
    // 2) second projection of q,k -> qh/ql (x0.125), kh/kl
    gemm_mma<3><<<dim3(16, 64), 128, GEMM_SMEM>>>(qkh, qkl, 2048, wih, wil, 1024,
                                                  b_in, nullptr, nullptr, nullptr, 1.0f, 1024, 1024);
    // 3) attention (2 CTAs/SM, 3-stage KV, single sync/iter) -> ctx hi/lo
    attn_mma<<<dim3(32, 16, 4), 128, ATT_SMEM>>>(qh, ql, kh, kl, vh, vl, mask, cth, ctl);
    // 4) out = ctx @ Wout^T + b (fp32 out)
    gemm_mma<0><<<dim3(8, 64), 128, GEMM_SMEM>>>(cth, ctl, 1024, woh, wol, 1024,
                                                 b_out, out, nullptr, nullptr, 1.0f, 1024, 1024);
}